// round 10
// baseline (speedup 1.0000x reference)
#include <cuda_runtime.h>
#include <cuda_bf16.h>
#include <math.h>
#include <stdint.h>

#define BS_TOK 16384
#define DIM    1024
#define DDIM   4096
#define NEXP   8
#define KCAP   2048   // tokens per expert

// ---------------- scratch (device globals; allocation-free rule) ----------
__device__ __align__(16) __nv_bfloat16 g_w1[(size_t)NEXP * DDIM * DIM];  // 64MB
__device__ __align__(16) __nv_bfloat16 g_w2[(size_t)NEXP * DIM * DDIM];  // 64MB
__device__ __align__(16) __nv_bfloat16 g_Y [(size_t)BS_TOK * DIM];       // 32MB
__device__ __align__(16) __nv_bfloat16 g_H [(size_t)BS_TOK * DDIM];     // 128MB
__device__ float    g_scores[NEXP * BS_TOK];
__device__ unsigned g_keys  [NEXP * BS_TOK];
__device__ int      g_selidx[BS_TOK];
__device__ float    g_selw  [BS_TOK];

// ---------------- small helpers -------------------------------------------
__device__ __forceinline__ uint32_t smem_u32(const void* p) {
    uint32_t a;
    asm("{ .reg .u64 t; cvta.to.shared.u64 t, %1; cvt.u32.u64 %0, t; }"
        : "=r"(a) : "l"(p));
    return a;
}
template <int N>
__device__ __forceinline__ void cp_wait() {
    asm volatile("cp.async.wait_group %0;" :: "n"(N) : "memory");
}
__device__ __forceinline__ void red_add_f32(float* p, float v) {
    asm volatile("red.global.add.f32 [%0], %1;" :: "l"(p), "f"(v) : "memory");
}

// ---------------- weight conversion fp32 -> bf16 (both matrices) ----------
__global__ void convert_w_kernel(const float4* __restrict__ f1,
                                 const float4* __restrict__ f2) {
    size_t n = (size_t)NEXP * DDIM * DIM / 4;
    __nv_bfloat162* w1 = (__nv_bfloat162*)g_w1;
    __nv_bfloat162* w2 = (__nv_bfloat162*)g_w2;
    for (size_t i = (size_t)blockIdx.x * blockDim.x + threadIdx.x; i < n;
         i += (size_t)gridDim.x * blockDim.x) {
        float4 a = f1[i];
        w1[2*i]   = __floats2bfloat162_rn(a.x, a.y);
        w1[2*i+1] = __floats2bfloat162_rn(a.z, a.w);
        float4 b = f2[i];
        w2[2*i]   = __floats2bfloat162_rn(b.x, b.y);
        w2[2*i+1] = __floats2bfloat162_rn(b.z, b.w);
    }
}

// ---------------- gating: softmax(x @ gate_w^T), 2 tokens/block -----------
__global__ void gate_kernel(const float* __restrict__ x,
                            const float* __restrict__ gw) {
    int t0 = blockIdx.x * 2;
    int tid = threadIdx.x;
    const float4 x0 = ((const float4*)(x + (size_t)t0 * DIM))[tid];
    const float4 x1 = ((const float4*)(x + (size_t)(t0 + 1) * DIM))[tid];
    float a0[NEXP], a1[NEXP];
#pragma unroll
    for (int e = 0; e < NEXP; e++) {
        float4 wv = ((const float4*)(gw + (size_t)e * DIM))[tid];
        a0[e] = x0.x*wv.x + x0.y*wv.y + x0.z*wv.z + x0.w*wv.w;
        a1[e] = x1.x*wv.x + x1.y*wv.y + x1.z*wv.z + x1.w*wv.w;
    }
#pragma unroll
    for (int e = 0; e < NEXP; e++)
#pragma unroll
        for (int o = 16; o > 0; o >>= 1) {
            a0[e] += __shfl_xor_sync(0xffffffffu, a0[e], o);
            a1[e] += __shfl_xor_sync(0xffffffffu, a1[e], o);
        }

    __shared__ float sh[2][8][NEXP];
    __shared__ float lg[2][NEXP];
    int w = tid >> 5, l = tid & 31;
    if (l == 0)
#pragma unroll
        for (int e = 0; e < NEXP; e++) { sh[0][w][e] = a0[e]; sh[1][w][e] = a1[e]; }
    __syncthreads();
    if (tid < 16) {
        int tk = tid >> 3, e = tid & 7;
        float s = 0.f;
#pragma unroll
        for (int i = 0; i < 8; i++) s += sh[tk][i][e];
        lg[tk][e] = s;
    }
    __syncthreads();
    if (tid < 16) {
        int tk = tid >> 3, e = tid & 7;
        int t = t0 + tk;
        float mx = lg[tk][0];
#pragma unroll
        for (int i = 1; i < NEXP; i++) mx = fmaxf(mx, lg[tk][i]);
        float den = 0.f;
#pragma unroll
        for (int i = 0; i < NEXP; i++) den += expf(lg[tk][i] - mx);
        float sc = expf(lg[tk][e] - mx) / den;
        g_scores[e * BS_TOK + t] = sc;
        unsigned b = __float_as_uint(sc);
        b ^= (b >> 31) ? 0xFFFFFFFFu : 0x80000000u;
        g_keys[e * BS_TOK + t] = b;
    }
}

// ------- per-expert exact top-k: smem-cached keys, 8-bit radix select ------
#define TPK_T 1024
#define TPK_SMEM (BS_TOK * 4)    // 64KB dynamic: all keys of one expert

__global__ __launch_bounds__(TPK_T, 1) void topk_kernel() {
    extern __shared__ unsigned skeys[];          // [BS_TOK]
    __shared__ unsigned hist[256];
    __shared__ unsigned suf[256];
    __shared__ unsigned s_prefix;
    __shared__ int s_need, s_out;

    const int e = blockIdx.x;
    const int tid = threadIdx.x, lane = tid & 31;
    const unsigned* keys = g_keys + (size_t)e * BS_TOK;

#pragma unroll
    for (int i = 0; i < BS_TOK / (TPK_T * 4); i++) {
        uint4 v = ((const uint4*)keys)[tid + i * TPK_T];
        ((uint4*)skeys)[tid + i * TPK_T] = v;
    }
    if (tid == 0) { s_prefix = 0u; s_need = KCAP; s_out = 0; }
    __syncthreads();

#pragma unroll
    for (int p = 3; p >= 0; p--) {
        if (tid < 256) hist[tid] = 0u;
        __syncthreads();
        const int sh = p * 8;
        const unsigned maskHi = (p == 3) ? 0u : (0xFFFFFFFFu << ((p + 1) * 8));
        const unsigned pref = s_prefix;
        const int need = s_need;
#pragma unroll
        for (int i = 0; i < BS_TOK / TPK_T; i++) {
            unsigned k = skeys[tid + i * TPK_T];
            bool m = ((k & maskHi) == pref);
            unsigned bin = m ? ((k >> sh) & 255u) : 0xFFFFFFFFu;
            unsigned peers = __match_any_sync(0xffffffffu, bin);
            if (m && lane == (__ffs(peers) - 1))
                atomicAdd(&hist[bin], (unsigned)__popc(peers));
        }
        __syncthreads();
        if (tid < 256) suf[tid] = hist[tid];
        __syncthreads();
#pragma unroll
        for (int st = 1; st < 256; st <<= 1) {
            unsigned v = 0;
            if (tid < 256) v = suf[tid] + ((tid + st < 256) ? suf[tid + st] : 0u);
            __syncthreads();
            if (tid < 256) suf[tid] = v;
            __syncthreads();
        }
        if (tid < 256) {
            unsigned nxt = (tid == 255) ? 0u : suf[tid + 1];
            if ((int)suf[tid] >= need && (int)nxt < need) {
                s_prefix = pref | ((unsigned)tid << sh);
                s_need = need - (int)nxt;
            }
        }
        __syncthreads();
    }

    const unsigned T = s_prefix;
    const int needEq = s_need;
#pragma unroll
    for (int i = 0; i < BS_TOK / TPK_T; i++) {
        int t = tid + i * TPK_T;
        unsigned k = skeys[t];
        bool sel = false;
        if (k > T) sel = true;
        else if (k == T) {    // tie: lower index first (matches lax.top_k)
            int r = 0;
            for (int j = 0; j < t; j++) r += (skeys[j] == T);
            sel = (r < needEq);
        }
        if (sel) {
            int slot = atomicAdd(&s_out, 1);
            g_selidx[e * KCAP + slot] = t;
            g_selw  [e * KCAP + slot] = g_scores[(size_t)e * BS_TOK + t];
        }
    }
}

// ---------------- gather + layernorm -> bf16 Y (2 slots/block) ------------
__global__ void gather_ln_kernel(const float* __restrict__ x,
                                 const float* __restrict__ lnw,
                                 const float* __restrict__ lnb) {
    int g0 = blockIdx.x * 2;
    int tid = threadIdx.x;
    int tok0 = g_selidx[g0];
    int tok1 = g_selidx[g0 + 1];
    float4 v0 = ((const float4*)(x + (size_t)tok0 * DIM))[tid];
    float4 v1 = ((const float4*)(x + (size_t)tok1 * DIM))[tid];
    float s0 = v0.x + v0.y + v0.z + v0.w;
    float q0 = v0.x*v0.x + v0.y*v0.y + v0.z*v0.z + v0.w*v0.w;
    float s1 = v1.x + v1.y + v1.z + v1.w;
    float q1 = v1.x*v1.x + v1.y*v1.y + v1.z*v1.z + v1.w*v1.w;
#pragma unroll
    for (int o = 16; o > 0; o >>= 1) {
        s0 += __shfl_xor_sync(0xffffffffu, s0, o);
        q0 += __shfl_xor_sync(0xffffffffu, q0, o);
        s1 += __shfl_xor_sync(0xffffffffu, s1, o);
        q1 += __shfl_xor_sync(0xffffffffu, q1, o);
    }
    __shared__ float red[4][8];
    __shared__ float fin[4];
    int w = tid >> 5, l = tid & 31;
    if (l == 0) { red[0][w] = s0; red[1][w] = q0; red[2][w] = s1; red[3][w] = q1; }
    __syncthreads();
    if (tid < 2) {
        float S = 0.f, Q = 0.f;
#pragma unroll
        for (int i = 0; i < 8; i++) { S += red[2*tid][i]; Q += red[2*tid+1][i]; }
        float mu = S * (1.f / DIM);
        float var = Q * (1.f / DIM) - mu * mu;
        fin[2*tid]   = mu;
        fin[2*tid+1] = rsqrtf(var + 1e-5f);
    }
    __syncthreads();
    float mu0 = fin[0], rs0 = fin[1], mu1 = fin[2], rs1 = fin[3];
    float4 wv = ((const float4*)lnw)[tid];
    float4 bv = ((const float4*)lnb)[tid];
    __nv_bfloat162* y0 = (__nv_bfloat162*)(g_Y + (size_t)g0 * DIM);
    __nv_bfloat162* y1 = (__nv_bfloat162*)(g_Y + (size_t)(g0 + 1) * DIM);
    y0[tid*2]   = __floats2bfloat162_rn((v0.x-mu0)*rs0*wv.x + bv.x,
                                        (v0.y-mu0)*rs0*wv.y + bv.y);
    y0[tid*2+1] = __floats2bfloat162_rn((v0.z-mu0)*rs0*wv.z + bv.z,
                                        (v0.w-mu0)*rs0*wv.w + bv.w);
    y1[tid*2]   = __floats2bfloat162_rn((v1.x-mu1)*rs1*wv.x + bv.x,
                                        (v1.y-mu1)*rs1*wv.y + bv.y);
    y1[tid*2+1] = __floats2bfloat162_rn((v1.z-mu1)*rs1*wv.z + bv.z,
                                        (v1.w-mu1)*rs1*wv.w + bv.w);
}

// ---------------- mma.sync GEMM: 128x256x64 tiles, 4-stage cp.async --------
#define BM 128
#define BN 256
#define BK 64
#define NSTG 4
#define STGB ((BM + BN) * BK * 2)     // 49152 bytes per stage
#define GEMM_SMEM (NSTG * STGB)       // 196608

__device__ __forceinline__ float gelu_f(float v) {
    float u = 0.7978845608028654f * (v + 0.044715f * v * v * v);
    float e = __expf(2.f * u);
    float th = 1.f - __fdividef(2.f, e + 1.f);
    return 0.5f * v * (1.f + th);
}

// EPI==1: g_H = gelu(Y @ W1^T + b1) bf16.
// EPI==2: out[token] += (acc+b2)*selw  (red.global.add.f32 scatter).
template <int EPI, int M, int N, int K>
__global__ __launch_bounds__(256, 1) void mma_gemm(const float* __restrict__ bias,
                                                   float* __restrict__ outF) {
    extern __shared__ __align__(1024) char smdyn[];
    const int tid = threadIdx.x, wid = tid >> 5, lane = tid & 31;
    const int wm = wid >> 2, wn = wid & 3;           // 2 x 4 warps, 64x64 tiles
    const int e = blockIdx.z;
    uint32_t sb = smem_u32(smdyn);

    // CTA raster swizzle: walk 8 M-tiles fast, then N, for L2 reuse
    const int GX = N / BN;
    int lin = blockIdx.y * GX + blockIdx.x;
    int bm, bn;
    {
        int inb = lin % (8 * GX);
        int g2 = lin / (8 * GX);
        bm = g2 * 8 + (inb & 7);
        bn = inb >> 3;
    }

    const __nv_bfloat16* A = ((EPI == 1) ? g_Y : g_H) +
                             ((size_t)e * M + (size_t)bm * BM) * (size_t)K;
    const __nv_bfloat16* B = ((EPI == 1) ? g_w1 : g_w2) +
                             ((size_t)e * N + (size_t)bn * BN) * (size_t)K;

    __shared__ float bsm[BN];
    bsm[tid] = bias[(size_t)e * N + bn * BN + tid];

    auto fill = [&](int c, int s) {
        uint32_t abase = sb + s * STGB;
        uint32_t bbase = abase + BM * BK * 2;     // +16KB
        const __nv_bfloat16* ga = A + c * BK;
        const __nv_bfloat16* gb = B + c * BK;
#pragma unroll
        for (int t = 0; t < 4; t++) {
            int i = tid + t * 256;
            int row = i >> 3, seg = i & 7;
            uint32_t off = (uint32_t)(row * 128 + seg * 16);
            off ^= (off >> 3) & 0x70u;
            asm volatile("cp.async.cg.shared.global [%0], [%1], 16;"
                         :: "r"(abase + off), "l"(ga + (size_t)row * K + seg * 8));
        }
#pragma unroll
        for (int t = 0; t < 8; t++) {
            int i = tid + t * 256;
            int row = i >> 3, seg = i & 7;
            uint32_t off = (uint32_t)(row * 128 + seg * 16);
            off ^= (off >> 3) & 0x70u;
            asm volatile("cp.async.cg.shared.global [%0], [%1], 16;"
                         :: "r"(bbase + off), "l"(gb + (size_t)row * K + seg * 8));
        }
        asm volatile("cp.async.commit_group;" ::: "memory");
    };

    float c[4][8][4];
#pragma unroll
    for (int a = 0; a < 4; a++)
#pragma unroll
        for (int b = 0; b < 8; b++)
#pragma unroll
            for (int d = 0; d < 4; d++) c[a][b][d] = 0.f;

    const int nk = K / BK;
    fill(0, 0); fill(1, 1); fill(2, 2);

    for (int kc = 0; kc < nk; kc++) {
        int rem = nk - 1 - kc;
        if (rem >= 2) cp_wait<2>();
        else if (rem == 1) cp_wait<1>();
        else cp_wait<0>();
        __syncthreads();
        if (kc + 3 < nk) fill(kc + 3, (kc + 3) & 3);

        uint32_t abase = sb + (kc & 3) * STGB;
        uint32_t bbase = abase + BM * BK * 2;

#pragma unroll
        for (int ks = 0; ks < 4; ks++) {
            uint32_t a[4][4], b[8][2];
            int ar = wm * 64 + (lane & 15);
            int ac = ks * 32 + (lane >> 4) * 16;
#pragma unroll
            for (int mi = 0; mi < 4; mi++) {
                uint32_t off = (uint32_t)((ar + mi * 16) * 128 + ac);
                off ^= (off >> 3) & 0x70u;
                asm volatile(
                    "ldmatrix.sync.aligned.m8n8.x4.shared.b16 {%0,%1,%2,%3}, [%4];"
                    : "=r"(a[mi][0]), "=r"(a[mi][1]), "=r"(a[mi][2]), "=r"(a[mi][3])
                    : "r"(abase + off));
            }
            int nr = wn * 64 + (lane & 7) + ((lane >> 4) << 3);
            int kb = ks * 32 + ((lane >> 3) & 1) * 16;
#pragma unroll
            for (int nb = 0; nb < 4; nb++) {
                uint32_t off = (uint32_t)((nr + nb * 16) * 128 + kb);
                off ^= (off >> 3) & 0x70u;
                asm volatile(
                    "ldmatrix.sync.aligned.m8n8.x4.shared.b16 {%0,%1,%2,%3}, [%4];"
                    : "=r"(b[2*nb][0]), "=r"(b[2*nb][1]),
                      "=r"(b[2*nb+1][0]), "=r"(b[2*nb+1][1])
                    : "r"(bbase + off));
            }
#pragma unroll
            for (int mi = 0; mi < 4; mi++)
#pragma unroll
                for (int ni = 0; ni < 8; ni++) {
                    asm volatile(
                        "mma.sync.aligned.m16n8k16.row.col.f32.bf16.bf16.f32 "
                        "{%0,%1,%2,%3}, {%4,%5,%6,%7}, {%8,%9}, {%0,%1,%2,%3};"
                        : "+f"(c[mi][ni][0]), "+f"(c[mi][ni][1]),
                          "+f"(c[mi][ni][2]), "+f"(c[mi][ni][3])
                        : "r"(a[mi][0]), "r"(a[mi][1]), "r"(a[mi][2]), "r"(a[mi][3]),
                          "r"(b[ni][0]), "r"(b[ni][1]));
                }
        }
        __syncthreads();
    }

    // -------- epilogue --------
    int g4 = lane >> 2, tg2 = (lane & 3) * 2;
    if (EPI == 1) {
#pragma unroll
        for (int mi = 0; mi < 4; mi++) {
            int row = bm * BM + wm * 64 + mi * 16 + g4;
            size_t h0 = ((size_t)e * M + row) * (size_t)N;
            size_t h1 = ((size_t)e * M + row + 8) * (size_t)N;
#pragma unroll
            for (int ni = 0; ni < 8; ni++) {
                int lc = wn * 64 + ni * 8 + tg2;
                int col = bn * BN + lc;
                float bb0 = bsm[lc], bb1 = bsm[lc + 1];
                *(__nv_bfloat162*)(g_H + h0 + col) = __floats2bfloat162_rn(
                    gelu_f(c[mi][ni][0] + bb0), gelu_f(c[mi][ni][1] + bb1));
                *(__nv_bfloat162*)(g_H + h1 + col) = __floats2bfloat162_rn(
                    gelu_f(c[mi][ni][2] + bb0), gelu_f(c[mi][ni][3] + bb1));
            }
        }
    } else {
#pragma unroll
        for (int mi = 0; mi < 4; mi++) {
            int row = bm * BM + wm * 64 + mi * 16 + g4;
            int t0 = g_selidx[e * KCAP + row];
            int t1 = g_selidx[e * KCAP + row + 8];
            float w0 = g_selw[e * KCAP + row];
            float w1 = g_selw[e * KCAP + row + 8];
            float* d0 = outF + (size_t)t0 * DIM;
            float* d1 = outF + (size_t)t1 * DIM;
#pragma unroll
            for (int ni = 0; ni < 8; ni++) {
                int lc = wn * 64 + ni * 8 + tg2;
                int col = bn * BN + lc;
                float bb0 = bsm[lc], bb1 = bsm[lc + 1];
                red_add_f32(d0 + col,     (c[mi][ni][0] + bb0) * w0);
                red_add_f32(d0 + col + 1, (c[mi][ni][1] + bb1) * w0);
                red_add_f32(d1 + col,     (c[mi][ni][2] + bb0) * w1);
                red_add_f32(d1 + col + 1, (c[mi][ni][3] + bb1) * w1);
            }
        }
    }
}

// ---------------- launch ---------------------------------------------------
extern "C" void kernel_launch(void* const* d_in, const int* in_sizes, int n_in,
                              void* d_out, int out_size) {
    const float* x   = (const float*)d_in[0];
    const float* gw  = (const float*)d_in[1];
    const float* lnw = (const float*)d_in[2];
    const float* lnb = (const float*)d_in[3];
    const float* fc1 = (const float*)d_in[4];
    const float* b1  = (const float*)d_in[5];
    const float* fc2 = (const float*)d_in[6];
    const float* b2  = (const float*)d_in[7];
    float* out = (float*)d_out;

    cudaFuncSetAttribute(mma_gemm<1, KCAP, DDIM, DIM>,
                         cudaFuncAttributeMaxDynamicSharedMemorySize, GEMM_SMEM);
    cudaFuncSetAttribute(mma_gemm<2, KCAP, DIM, DDIM>,
                         cudaFuncAttributeMaxDynamicSharedMemorySize, GEMM_SMEM);
    cudaFuncSetAttribute(topk_kernel,
                         cudaFuncAttributeMaxDynamicSharedMemorySize, TPK_SMEM);

    // fork: side stream does convert_w (~56us, DRAM-bound) then out<-x seed;
    // both overlap the routing chain / GEMM1. Join points: GEMM1 needs evW
    // (weights), GEMM2 needs evSeed (output seeded).
    cudaStream_t sB;
    cudaStreamCreateWithFlags(&sB, cudaStreamNonBlocking);
    cudaEvent_t evFork, evW, evSeed;
    cudaEventCreateWithFlags(&evFork, cudaEventDisableTiming);
    cudaEventCreateWithFlags(&evW,    cudaEventDisableTiming);
    cudaEventCreateWithFlags(&evSeed, cudaEventDisableTiming);

    cudaEventRecord(evFork, 0);
    cudaStreamWaitEvent(sB, evFork, 0);
    convert_w_kernel<<<4096, 256, 0, sB>>>((const float4*)fc1,
                                           (const float4*)fc2);
    cudaEventRecord(evW, sB);
    cudaMemcpyAsync(out, x, (size_t)BS_TOK * DIM * sizeof(float),
                    cudaMemcpyDeviceToDevice, sB);
    cudaEventRecord(evSeed, sB);

    gate_kernel<<<BS_TOK / 2, 256>>>(x, gw);
    topk_kernel<<<NEXP, TPK_T, TPK_SMEM>>>();
    gather_ln_kernel<<<BS_TOK / 2, 256>>>(x, lnw, lnb);

    cudaStreamWaitEvent(0, evW, 0);                   // weights ready
    {   // GEMM1: per expert (2048 x 4096 x 1024), fused bias + gelu -> g_H
        dim3 grid(DDIM / BN, KCAP / BM, NEXP);   // (16, 16, 8)
        mma_gemm<1, KCAP, DDIM, DIM><<<grid, 256, GEMM_SMEM>>>(b1, nullptr);
    }
    cudaStreamWaitEvent(0, evSeed, 0);                // out seeded with x
    {   // GEMM2: per expert (2048 x 1024 x 4096), bias+scale+scatter-add
        dim3 grid(DIM / BN, KCAP / BM, NEXP);    // (4, 16, 8)
        mma_gemm<2, KCAP, DIM, DDIM><<<grid, 256, GEMM_SMEM>>>(b2, out);
    }
}

// round 11
// speedup vs baseline: 1.0122x; 1.0122x over previous
#include <cuda_runtime.h>
#include <cuda_bf16.h>
#include <math.h>
#include <stdint.h>

#define BS_TOK 16384
#define DIM    1024
#define DDIM   4096
#define NEXP   8
#define KCAP   2048   // tokens per expert

// ---------------- scratch (device globals; allocation-free rule) ----------
__device__ __align__(16) __nv_bfloat16 g_w1 [(size_t)NEXP * DDIM * DIM]; // 64MB
__device__ __align__(16) __nv_bfloat16 g_w2 [(size_t)NEXP * DIM * DDIM]; // 64MB
__device__ __align__(16) __nv_bfloat16 g_xln[(size_t)BS_TOK * DIM];      // 32MB (token-ordered LN(x))
__device__ __align__(16) __nv_bfloat16 g_H  [(size_t)BS_TOK * DDIM];    // 128MB
__device__ __align__(16) float g_O[(size_t)BS_TOK * DIM];                // 64MB
__device__ float    g_scores[NEXP * BS_TOK];
__device__ unsigned g_keys  [NEXP * BS_TOK];
__device__ int      g_selidx[BS_TOK];
__device__ float    g_selw  [BS_TOK];
__device__ int      g_t2s   [BS_TOK * NEXP];   // token -> slot (or -1)

// ---------------- small helpers -------------------------------------------
__device__ __forceinline__ uint32_t smem_u32(const void* p) {
    uint32_t a;
    asm("{ .reg .u64 t; cvta.to.shared.u64 t, %1; cvt.u32.u64 %0, t; }"
        : "=r"(a) : "l"(p));
    return a;
}
template <int N>
__device__ __forceinline__ void cp_wait() {
    asm volatile("cp.async.wait_group %0;" :: "n"(N) : "memory");
}

// ---------------- weight conversion fp32 -> bf16 (one matrix) -------------
// which==1 -> g_w1, which==2 -> g_w2 (device-side symbol select)
__global__ void convert_w_kernel(const float4* __restrict__ src, int which) {
    size_t n = (size_t)NEXP * DDIM * DIM / 4;
    __nv_bfloat162* dst = (which == 1) ? (__nv_bfloat162*)g_w1
                                       : (__nv_bfloat162*)g_w2;
    for (size_t i = (size_t)blockIdx.x * blockDim.x + threadIdx.x; i < n;
         i += (size_t)gridDim.x * blockDim.x) {
        float4 a = src[i];
        dst[2*i]   = __floats2bfloat162_rn(a.x, a.y);
        dst[2*i+1] = __floats2bfloat162_rn(a.z, a.w);
    }
}

// -------- gating + LayerNorm fused: softmax scores + x_ln, 2 tok/block -----
__global__ void gate_ln_kernel(const float* __restrict__ x,
                               const float* __restrict__ gw,
                               const float* __restrict__ lnw,
                               const float* __restrict__ lnb) {
    int t0 = blockIdx.x * 2;
    int tid = threadIdx.x;
    if (tid < 2 * NEXP) g_t2s[t0 * NEXP + tid] = -1;   // fold t2s init
    const float4 x0 = ((const float4*)(x + (size_t)t0 * DIM))[tid];
    const float4 x1 = ((const float4*)(x + (size_t)(t0 + 1) * DIM))[tid];
    float a0[NEXP], a1[NEXP];
#pragma unroll
    for (int e = 0; e < NEXP; e++) {
        float4 wv = ((const float4*)(gw + (size_t)e * DIM))[tid];
        a0[e] = x0.x*wv.x + x0.y*wv.y + x0.z*wv.z + x0.w*wv.w;
        a1[e] = x1.x*wv.x + x1.y*wv.y + x1.z*wv.z + x1.w*wv.w;
    }
    float s0 = x0.x + x0.y + x0.z + x0.w;
    float q0 = x0.x*x0.x + x0.y*x0.y + x0.z*x0.z + x0.w*x0.w;
    float s1 = x1.x + x1.y + x1.z + x1.w;
    float q1 = x1.x*x1.x + x1.y*x1.y + x1.z*x1.z + x1.w*x1.w;
#pragma unroll
    for (int o = 16; o > 0; o >>= 1) {
#pragma unroll
        for (int e = 0; e < NEXP; e++) {
            a0[e] += __shfl_xor_sync(0xffffffffu, a0[e], o);
            a1[e] += __shfl_xor_sync(0xffffffffu, a1[e], o);
        }
        s0 += __shfl_xor_sync(0xffffffffu, s0, o);
        q0 += __shfl_xor_sync(0xffffffffu, q0, o);
        s1 += __shfl_xor_sync(0xffffffffu, s1, o);
        q1 += __shfl_xor_sync(0xffffffffu, q1, o);
    }

    __shared__ float sh[2][8][NEXP];
    __shared__ float red[4][8];
    __shared__ float lg[2][NEXP];
    __shared__ float fin[4];
    int w = tid >> 5, l = tid & 31;
    if (l == 0) {
#pragma unroll
        for (int e = 0; e < NEXP; e++) { sh[0][w][e] = a0[e]; sh[1][w][e] = a1[e]; }
        red[0][w] = s0; red[1][w] = q0; red[2][w] = s1; red[3][w] = q1;
    }
    __syncthreads();
    if (tid < 16) {
        int tk = tid >> 3, e = tid & 7;
        float s = 0.f;
#pragma unroll
        for (int i = 0; i < 8; i++) s += sh[tk][i][e];
        lg[tk][e] = s;
    }
    if (tid >= 32 && tid < 34) {
        int tk = tid - 32;
        float S = 0.f, Q = 0.f;
#pragma unroll
        for (int i = 0; i < 8; i++) { S += red[2*tk][i]; Q += red[2*tk+1][i]; }
        float mu = S * (1.f / DIM);
        float var = Q * (1.f / DIM) - mu * mu;
        fin[2*tk]   = mu;
        fin[2*tk+1] = rsqrtf(var + 1e-5f);
    }
    __syncthreads();
    if (tid < 16) {
        int tk = tid >> 3, e = tid & 7;
        int t = t0 + tk;
        float mx = lg[tk][0];
#pragma unroll
        for (int i = 1; i < NEXP; i++) mx = fmaxf(mx, lg[tk][i]);
        float den = 0.f;
#pragma unroll
        for (int i = 0; i < NEXP; i++) den += expf(lg[tk][i] - mx);
        float sc = expf(lg[tk][e] - mx) / den;
        g_scores[e * BS_TOK + t] = sc;
        unsigned b = __float_as_uint(sc);
        b ^= (b >> 31) ? 0xFFFFFFFFu : 0x80000000u;
        g_keys[e * BS_TOK + t] = b;
    }
    float mu0 = fin[0], rs0 = fin[1], mu1 = fin[2], rs1 = fin[3];
    float4 wv = ((const float4*)lnw)[tid];
    float4 bv = ((const float4*)lnb)[tid];
    __nv_bfloat162* y0 = (__nv_bfloat162*)(g_xln + (size_t)t0 * DIM);
    __nv_bfloat162* y1 = (__nv_bfloat162*)(g_xln + (size_t)(t0 + 1) * DIM);
    y0[tid*2]   = __floats2bfloat162_rn((x0.x-mu0)*rs0*wv.x + bv.x,
                                        (x0.y-mu0)*rs0*wv.y + bv.y);
    y0[tid*2+1] = __floats2bfloat162_rn((x0.z-mu0)*rs0*wv.z + bv.z,
                                        (x0.w-mu0)*rs0*wv.w + bv.w);
    y1[tid*2]   = __floats2bfloat162_rn((x1.x-mu1)*rs1*wv.x + bv.x,
                                        (x1.y-mu1)*rs1*wv.y + bv.y);
    y1[tid*2+1] = __floats2bfloat162_rn((x1.z-mu1)*rs1*wv.z + bv.z,
                                        (x1.w-mu1)*rs1*wv.w + bv.w);
}

// ------- per-expert exact top-k: smem-cached keys, 8-bit radix select ------
#define TPK_T 1024
#define TPK_SMEM (BS_TOK * 4)    // 64KB dynamic: all keys of one expert

__global__ __launch_bounds__(TPK_T, 1) void topk_kernel() {
    extern __shared__ unsigned skeys[];          // [BS_TOK]
    __shared__ unsigned hist[256];
    __shared__ unsigned suf[256];
    __shared__ unsigned s_prefix;
    __shared__ int s_need, s_out;

    const int e = blockIdx.x;
    const int tid = threadIdx.x, lane = tid & 31;
    const unsigned* keys = g_keys + (size_t)e * BS_TOK;

#pragma unroll
    for (int i = 0; i < BS_TOK / (TPK_T * 4); i++) {
        uint4 v = ((const uint4*)keys)[tid + i * TPK_T];
        ((uint4*)skeys)[tid + i * TPK_T] = v;
    }
    if (tid == 0) { s_prefix = 0u; s_need = KCAP; s_out = 0; }
    __syncthreads();

#pragma unroll
    for (int p = 3; p >= 0; p--) {
        if (tid < 256) hist[tid] = 0u;
        __syncthreads();
        const int sh = p * 8;
        const unsigned maskHi = (p == 3) ? 0u : (0xFFFFFFFFu << ((p + 1) * 8));
        const unsigned pref = s_prefix;
        const int need = s_need;
#pragma unroll
        for (int i = 0; i < BS_TOK / TPK_T; i++) {
            unsigned k = skeys[tid + i * TPK_T];
            bool m = ((k & maskHi) == pref);
            unsigned bin = m ? ((k >> sh) & 255u) : 0xFFFFFFFFu;
            unsigned peers = __match_any_sync(0xffffffffu, bin);
            if (m && lane == (__ffs(peers) - 1))
                atomicAdd(&hist[bin], (unsigned)__popc(peers));
        }
        __syncthreads();
        if (tid < 256) suf[tid] = hist[tid];
        __syncthreads();
#pragma unroll
        for (int st = 1; st < 256; st <<= 1) {
            unsigned v = 0;
            if (tid < 256) v = suf[tid] + ((tid + st < 256) ? suf[tid + st] : 0u);
            __syncthreads();
            if (tid < 256) suf[tid] = v;
            __syncthreads();
        }
        if (tid < 256) {
            unsigned nxt = (tid == 255) ? 0u : suf[tid + 1];
            if ((int)suf[tid] >= need && (int)nxt < need) {
                s_prefix = pref | ((unsigned)tid << sh);
                s_need = need - (int)nxt;
            }
        }
        __syncthreads();
    }

    const unsigned T = s_prefix;
    const int needEq = s_need;
#pragma unroll
    for (int i = 0; i < BS_TOK / TPK_T; i++) {
        int t = tid + i * TPK_T;
        unsigned k = skeys[t];
        bool sel = false;
        if (k > T) sel = true;
        else if (k == T) {    // tie: lower index first (matches lax.top_k)
            int r = 0;
            for (int j = 0; j < t; j++) r += (skeys[j] == T);
            sel = (r < needEq);
        }
        if (sel) {
            int slot = atomicAdd(&s_out, 1);
            g_selidx[e * KCAP + slot] = t;
            g_selw  [e * KCAP + slot] = g_scores[(size_t)e * BS_TOK + t];
            g_t2s[t * NEXP + e] = e * KCAP + slot;
        }
    }
}

// ---------------- mma.sync GEMM: 128x256x64 tiles, 4-stage cp.async --------
// EPI==1: A rows gathered from g_xln via g_selidx (slot -> token).
#define BM 128
#define BN 256
#define BK 64
#define NSTG 4
#define STGB ((BM + BN) * BK * 2)     // 49152 bytes per stage
#define GEMM_SMEM (NSTG * STGB)       // 196608

__device__ __forceinline__ float gelu_f(float v) {
    float u = 0.7978845608028654f * (v + 0.044715f * v * v * v);
    float e = __expf(2.f * u);
    float th = 1.f - __fdividef(2.f, e + 1.f);
    return 0.5f * v * (1.f + th);
}

// EPI==1: g_H = gelu(LN(x)[tok] @ W1^T + b1) bf16.  EPI==2: g_O[slot]=(acc+b2)*w
template <int EPI, int M, int N, int K>
__global__ __launch_bounds__(256, 1) void mma_gemm(const float* __restrict__ bias) {
    extern __shared__ __align__(1024) char smdyn[];
    const int tid = threadIdx.x, wid = tid >> 5, lane = tid & 31;
    const int wm = wid >> 2, wn = wid & 3;           // 2 x 4 warps, 64x64 tiles
    const int e = blockIdx.z;
    uint32_t sb = smem_u32(smdyn);

    // CTA raster swizzle: walk 8 M-tiles fast, then N, for L2 reuse
    const int GX = N / BN;
    int lin = blockIdx.y * GX + blockIdx.x;
    int bm, bn;
    {
        int inb = lin % (8 * GX);
        int g2 = lin / (8 * GX);
        bm = g2 * 8 + (inb & 7);
        bn = inb >> 3;
    }

    const __nv_bfloat16* B = ((EPI == 1) ? g_w1 : g_w2) +
                             ((size_t)e * N + (size_t)bn * BN) * (size_t)K;
    const __nv_bfloat16* A2 = g_H + ((size_t)e * M + (size_t)bm * BM) * (size_t)K;

    __shared__ float bsm[BN];
    __shared__ int stok[BM];          // slot -> token map (EPI==1 gather)
    bsm[tid] = bias[(size_t)e * N + bn * BN + tid];
    if (EPI == 1 && tid < BM) stok[tid] = g_selidx[e * KCAP + bm * BM + tid];
    __syncthreads();

    auto fill = [&](int c, int s) {
        uint32_t abase = sb + s * STGB;
        uint32_t bbase = abase + BM * BK * 2;     // +16KB
        const __nv_bfloat16* gb = B + c * BK;
#pragma unroll
        for (int t = 0; t < 4; t++) {             // A: 1024 16B-chunks
            int i = tid + t * 256;
            int row = i >> 3, seg = i & 7;
            uint32_t off = (uint32_t)(row * 128 + seg * 16);
            off ^= (off >> 3) & 0x70u;
            const __nv_bfloat16* ga;
            if (EPI == 1)
                ga = g_xln + (size_t)stok[row] * K + c * BK + seg * 8;
            else
                ga = A2 + (size_t)row * K + c * BK + seg * 8;
            asm volatile("cp.async.cg.shared.global [%0], [%1], 16;"
                         :: "r"(abase + off), "l"(ga));
        }
#pragma unroll
        for (int t = 0; t < 8; t++) {             // B: 2048 16B-chunks
            int i = tid + t * 256;
            int row = i >> 3, seg = i & 7;
            uint32_t off = (uint32_t)(row * 128 + seg * 16);
            off ^= (off >> 3) & 0x70u;
            asm volatile("cp.async.cg.shared.global [%0], [%1], 16;"
                         :: "r"(bbase + off), "l"(gb + (size_t)row * K + seg * 8));
        }
        asm volatile("cp.async.commit_group;" ::: "memory");
    };

    float c[4][8][4];
#pragma unroll
    for (int a = 0; a < 4; a++)
#pragma unroll
        for (int b = 0; b < 8; b++)
#pragma unroll
            for (int d = 0; d < 4; d++) c[a][b][d] = 0.f;

    const int nk = K / BK;
    fill(0, 0); fill(1, 1); fill(2, 2);

    for (int kc = 0; kc < nk; kc++) {
        int rem = nk - 1 - kc;
        if (rem >= 2) cp_wait<2>();
        else if (rem == 1) cp_wait<1>();
        else cp_wait<0>();
        __syncthreads();
        if (kc + 3 < nk) fill(kc + 3, (kc + 3) & 3);

        uint32_t abase = sb + (kc & 3) * STGB;
        uint32_t bbase = abase + BM * BK * 2;

#pragma unroll
        for (int ks = 0; ks < 4; ks++) {
            uint32_t a[4][4], b[8][2];
            int ar = wm * 64 + (lane & 15);
            int ac = ks * 32 + (lane >> 4) * 16;
#pragma unroll
            for (int mi = 0; mi < 4; mi++) {
                uint32_t off = (uint32_t)((ar + mi * 16) * 128 + ac);
                off ^= (off >> 3) & 0x70u;
                asm volatile(
                    "ldmatrix.sync.aligned.m8n8.x4.shared.b16 {%0,%1,%2,%3}, [%4];"
                    : "=r"(a[mi][0]), "=r"(a[mi][1]), "=r"(a[mi][2]), "=r"(a[mi][3])
                    : "r"(abase + off));
            }
            int nr = wn * 64 + (lane & 7) + ((lane >> 4) << 3);
            int kb = ks * 32 + ((lane >> 3) & 1) * 16;
#pragma unroll
            for (int nb = 0; nb < 4; nb++) {
                uint32_t off = (uint32_t)((nr + nb * 16) * 128 + kb);
                off ^= (off >> 3) & 0x70u;
                asm volatile(
                    "ldmatrix.sync.aligned.m8n8.x4.shared.b16 {%0,%1,%2,%3}, [%4];"
                    : "=r"(b[2*nb][0]), "=r"(b[2*nb][1]),
                      "=r"(b[2*nb+1][0]), "=r"(b[2*nb+1][1])
                    : "r"(bbase + off));
            }
#pragma unroll
            for (int mi = 0; mi < 4; mi++)
#pragma unroll
                for (int ni = 0; ni < 8; ni++) {
                    asm volatile(
                        "mma.sync.aligned.m16n8k16.row.col.f32.bf16.bf16.f32 "
                        "{%0,%1,%2,%3}, {%4,%5,%6,%7}, {%8,%9}, {%0,%1,%2,%3};"
                        : "+f"(c[mi][ni][0]), "+f"(c[mi][ni][1]),
                          "+f"(c[mi][ni][2]), "+f"(c[mi][ni][3])
                        : "r"(a[mi][0]), "r"(a[mi][1]), "r"(a[mi][2]), "r"(a[mi][3]),
                          "r"(b[ni][0]), "r"(b[ni][1]));
                }
        }
        __syncthreads();
    }

    // -------- epilogue --------
    int g4 = lane >> 2, tg2 = (lane & 3) * 2;
    if (EPI == 1) {
#pragma unroll
        for (int mi = 0; mi < 4; mi++) {
            int row = bm * BM + wm * 64 + mi * 16 + g4;
            size_t h0 = ((size_t)e * M + row) * (size_t)N;
            size_t h1 = ((size_t)e * M + row + 8) * (size_t)N;
#pragma unroll
            for (int ni = 0; ni < 8; ni++) {
                int lc = wn * 64 + ni * 8 + tg2;
                int col = bn * BN + lc;
                float bb0 = bsm[lc], bb1 = bsm[lc + 1];
                *(__nv_bfloat162*)(g_H + h0 + col) = __floats2bfloat162_rn(
                    gelu_f(c[mi][ni][0] + bb0), gelu_f(c[mi][ni][1] + bb1));
                *(__nv_bfloat162*)(g_H + h1 + col) = __floats2bfloat162_rn(
                    gelu_f(c[mi][ni][2] + bb0), gelu_f(c[mi][ni][3] + bb1));
            }
        }
    } else {
#pragma unroll
        for (int mi = 0; mi < 4; mi++) {
            int row = bm * BM + wm * 64 + mi * 16 + g4;
            float w0 = g_selw[e * KCAP + row];
            float w1 = g_selw[e * KCAP + row + 8];
            size_t o0 = ((size_t)e * M + row) * (size_t)N;
            size_t o1 = ((size_t)e * M + row + 8) * (size_t)N;
#pragma unroll
            for (int ni = 0; ni < 8; ni++) {
                int lc = wn * 64 + ni * 8 + tg2;
                int col = bn * BN + lc;
                float bb0 = bsm[lc], bb1 = bsm[lc + 1];
                float2 v0 = make_float2((c[mi][ni][0] + bb0) * w0,
                                        (c[mi][ni][1] + bb1) * w0);
                float2 v1 = make_float2((c[mi][ni][2] + bb0) * w1,
                                        (c[mi][ni][3] + bb1) * w1);
                *(float2*)(g_O + o0 + col) = v0;
                *(float2*)(g_O + o1 + col) = v1;
            }
        }
    }
}

// ---------------- final combine (2 tokens/block) ---------------------------
__global__ void combine_kernel(const float* __restrict__ x,
                               float* __restrict__ out) {
    int t0 = blockIdx.x * 2;
    int t1 = t0 + 1;
    int j = threadIdx.x;
    __shared__ int sl[2][NEXP];
    if (j < NEXP) sl[0][j] = g_t2s[t0 * NEXP + j];
    else if (j < 2 * NEXP) sl[1][j - NEXP] = g_t2s[t1 * NEXP + (j - NEXP)];
    float4 a0 = ((const float4*)(x + (size_t)t0 * DIM))[j];
    float4 a1 = ((const float4*)(x + (size_t)t1 * DIM))[j];
    __syncthreads();
#pragma unroll
    for (int e = 0; e < NEXP; e++) {
        int s0 = sl[0][e], s1 = sl[1][e];
        if (s0 >= 0) {
            float4 o = ((const float4*)(g_O + (size_t)s0 * DIM))[j];
            a0.x += o.x; a0.y += o.y; a0.z += o.z; a0.w += o.w;
        }
        if (s1 >= 0) {
            float4 o = ((const float4*)(g_O + (size_t)s1 * DIM))[j];
            a1.x += o.x; a1.y += o.y; a1.z += o.z; a1.w += o.w;
        }
    }
    ((float4*)(out + (size_t)t0 * DIM))[j] = a0;
    ((float4*)(out + (size_t)t1 * DIM))[j] = a1;
}

// ---------------- launch ---------------------------------------------------
extern "C" void kernel_launch(void* const* d_in, const int* in_sizes, int n_in,
                              void* d_out, int out_size) {
    const float* x   = (const float*)d_in[0];
    const float* gw  = (const float*)d_in[1];
    const float* lnw = (const float*)d_in[2];
    const float* lnb = (const float*)d_in[3];
    const float* fc1 = (const float*)d_in[4];
    const float* b1  = (const float*)d_in[5];
    const float* fc2 = (const float*)d_in[6];
    const float* b2  = (const float*)d_in[7];
    float* out = (float*)d_out;

    cudaFuncSetAttribute(mma_gemm<1, KCAP, DDIM, DIM>,
                         cudaFuncAttributeMaxDynamicSharedMemorySize, GEMM_SMEM);
    cudaFuncSetAttribute(mma_gemm<2, KCAP, DIM, DDIM>,
                         cudaFuncAttributeMaxDynamicSharedMemorySize, GEMM_SMEM);
    cudaFuncSetAttribute(topk_kernel,
                         cudaFuncAttributeMaxDynamicSharedMemorySize, TPK_SMEM);

    // fork: side stream converts w1 (joins GEMM1) then w2 (joins GEMM2,
    // hidden under GEMM1). Main stream: gate_ln -> topk (prologue ~50us).
    cudaStream_t sB;
    cudaStreamCreateWithFlags(&sB, cudaStreamNonBlocking);
    cudaEvent_t evFork, evW1, evW2;
    cudaEventCreateWithFlags(&evFork, cudaEventDisableTiming);
    cudaEventCreateWithFlags(&evW1,   cudaEventDisableTiming);
    cudaEventCreateWithFlags(&evW2,   cudaEventDisableTiming);

    cudaEventRecord(evFork, 0);
    cudaStreamWaitEvent(sB, evFork, 0);
    convert_w_kernel<<<4096, 256, 0, sB>>>((const float4*)fc1, 1);
    cudaEventRecord(evW1, sB);
    convert_w_kernel<<<4096, 256, 0, sB>>>((const float4*)fc2, 2);
    cudaEventRecord(evW2, sB);

    gate_ln_kernel<<<BS_TOK / 2, 256>>>(x, gw, lnw, lnb);  // scores + x_ln + t2s init
    topk_kernel<<<NEXP, TPK_T, TPK_SMEM>>>();

    cudaStreamWaitEvent(0, evW1, 0);                  // w1 ready
    {   // GEMM1: per expert (2048 x 4096 x 1024), A gathered from x_ln
        dim3 grid(DDIM / BN, KCAP / BM, NEXP);   // (16, 16, 8)
        mma_gemm<1, KCAP, DDIM, DIM><<<grid, 256, GEMM_SMEM>>>(b1);
    }
    cudaStreamWaitEvent(0, evW2, 0);                  // w2 ready
    {   // GEMM2: per expert (2048 x 1024 x 4096), bias + gate scale -> g_O
        dim3 grid(DIM / BN, KCAP / BM, NEXP);    // (4, 16, 8)
        mma_gemm<2, KCAP, DIM, DDIM><<<grid, 256, GEMM_SMEM>>>(b2);
    }
    combine_kernel<<<BS_TOK / 2, 256>>>(x, out);
}

// round 12
// speedup vs baseline: 1.0900x; 1.0769x over previous
#include <cuda_runtime.h>
#include <cuda_bf16.h>
#include <math.h>
#include <stdint.h>

#define BS_TOK 16384
#define DIM    1024
#define DDIM   4096
#define NEXP   8
#define KCAP   2048   // tokens per expert

// ---------------- scratch (device globals; allocation-free rule) ----------
__device__ __align__(16) __nv_bfloat16 g_w1 [(size_t)NEXP * DDIM * DIM]; // 64MB
__device__ __align__(16) __nv_bfloat16 g_w2 [(size_t)NEXP * DIM * DDIM]; // 64MB
__device__ __align__(16) __nv_bfloat16 g_xln[(size_t)BS_TOK * DIM];      // 32MB (token-ordered LN(x))
__device__ __align__(16) __nv_bfloat16 g_H  [(size_t)BS_TOK * DDIM];    // 128MB
__device__ __align__(16) float g_O[(size_t)BS_TOK * DIM];                // 64MB
__device__ float    g_scores[NEXP * BS_TOK];
__device__ unsigned g_keys  [NEXP * BS_TOK];
__device__ int      g_selidx[BS_TOK];
__device__ float    g_selw  [BS_TOK];
__device__ int      g_t2s   [BS_TOK * NEXP];   // token -> slot (or -1)

// ---------------- small helpers -------------------------------------------
__device__ __forceinline__ uint32_t smem_u32(const void* p) {
    uint32_t a;
    asm("{ .reg .u64 t; cvta.to.shared.u64 t, %1; cvt.u32.u64 %0, t; }"
        : "=r"(a) : "l"(p));
    return a;
}
template <int N>
__device__ __forceinline__ void cp_wait() {
    asm volatile("cp.async.wait_group %0;" :: "n"(N) : "memory");
}

// ---------------- weight conversion fp32 -> bf16 (one matrix) -------------
__global__ void convert_w_kernel(const float4* __restrict__ src, int which) {
    size_t n = (size_t)NEXP * DDIM * DIM / 4;
    __nv_bfloat162* dst = (which == 1) ? (__nv_bfloat162*)g_w1
                                       : (__nv_bfloat162*)g_w2;
    for (size_t i = (size_t)blockIdx.x * blockDim.x + threadIdx.x; i < n;
         i += (size_t)gridDim.x * blockDim.x) {
        float4 a = src[i];
        dst[2*i]   = __floats2bfloat162_rn(a.x, a.y);
        dst[2*i+1] = __floats2bfloat162_rn(a.z, a.w);
    }
}

// -------- gating + LayerNorm fused: softmax scores + x_ln, 2 tok/block -----
__global__ void gate_ln_kernel(const float* __restrict__ x,
                               const float* __restrict__ gw,
                               const float* __restrict__ lnw,
                               const float* __restrict__ lnb) {
    int t0 = blockIdx.x * 2;
    int tid = threadIdx.x;
    if (tid < 2 * NEXP) g_t2s[t0 * NEXP + tid] = -1;   // fold t2s init
    const float4 x0 = ((const float4*)(x + (size_t)t0 * DIM))[tid];
    const float4 x1 = ((const float4*)(x + (size_t)(t0 + 1) * DIM))[tid];
    float a0[NEXP], a1[NEXP];
#pragma unroll
    for (int e = 0; e < NEXP; e++) {
        float4 wv = ((const float4*)(gw + (size_t)e * DIM))[tid];
        a0[e] = x0.x*wv.x + x0.y*wv.y + x0.z*wv.z + x0.w*wv.w;
        a1[e] = x1.x*wv.x + x1.y*wv.y + x1.z*wv.z + x1.w*wv.w;
    }
    float s0 = x0.x + x0.y + x0.z + x0.w;
    float q0 = x0.x*x0.x + x0.y*x0.y + x0.z*x0.z + x0.w*x0.w;
    float s1 = x1.x + x1.y + x1.z + x1.w;
    float q1 = x1.x*x1.x + x1.y*x1.y + x1.z*x1.z + x1.w*x1.w;
#pragma unroll
    for (int o = 16; o > 0; o >>= 1) {
#pragma unroll
        for (int e = 0; e < NEXP; e++) {
            a0[e] += __shfl_xor_sync(0xffffffffu, a0[e], o);
            a1[e] += __shfl_xor_sync(0xffffffffu, a1[e], o);
        }
        s0 += __shfl_xor_sync(0xffffffffu, s0, o);
        q0 += __shfl_xor_sync(0xffffffffu, q0, o);
        s1 += __shfl_xor_sync(0xffffffffu, s1, o);
        q1 += __shfl_xor_sync(0xffffffffu, q1, o);
    }

    __shared__ float sh[2][8][NEXP];
    __shared__ float red[4][8];
    __shared__ float lg[2][NEXP];
    __shared__ float fin[4];
    int w = tid >> 5, l = tid & 31;
    if (l == 0) {
#pragma unroll
        for (int e = 0; e < NEXP; e++) { sh[0][w][e] = a0[e]; sh[1][w][e] = a1[e]; }
        red[0][w] = s0; red[1][w] = q0; red[2][w] = s1; red[3][w] = q1;
    }
    __syncthreads();
    if (tid < 16) {
        int tk = tid >> 3, e = tid & 7;
        float s = 0.f;
#pragma unroll
        for (int i = 0; i < 8; i++) s += sh[tk][i][e];
        lg[tk][e] = s;
    }
    if (tid >= 32 && tid < 34) {
        int tk = tid - 32;
        float S = 0.f, Q = 0.f;
#pragma unroll
        for (int i = 0; i < 8; i++) { S += red[2*tk][i]; Q += red[2*tk+1][i]; }
        float mu = S * (1.f / DIM);
        float var = Q * (1.f / DIM) - mu * mu;
        fin[2*tk]   = mu;
        fin[2*tk+1] = rsqrtf(var + 1e-5f);
    }
    __syncthreads();
    if (tid < 16) {
        int tk = tid >> 3, e = tid & 7;
        int t = t0 + tk;
        float mx = lg[tk][0];
#pragma unroll
        for (int i = 1; i < NEXP; i++) mx = fmaxf(mx, lg[tk][i]);
        float den = 0.f;
#pragma unroll
        for (int i = 0; i < NEXP; i++) den += expf(lg[tk][i] - mx);
        float sc = expf(lg[tk][e] - mx) / den;
        g_scores[e * BS_TOK + t] = sc;
        unsigned b = __float_as_uint(sc);
        b ^= (b >> 31) ? 0xFFFFFFFFu : 0x80000000u;
        g_keys[e * BS_TOK + t] = b;
    }
    float mu0 = fin[0], rs0 = fin[1], mu1 = fin[2], rs1 = fin[3];
    float4 wv = ((const float4*)lnw)[tid];
    float4 bv = ((const float4*)lnb)[tid];
    __nv_bfloat162* y0 = (__nv_bfloat162*)(g_xln + (size_t)t0 * DIM);
    __nv_bfloat162* y1 = (__nv_bfloat162*)(g_xln + (size_t)(t0 + 1) * DIM);
    y0[tid*2]   = __floats2bfloat162_rn((x0.x-mu0)*rs0*wv.x + bv.x,
                                        (x0.y-mu0)*rs0*wv.y + bv.y);
    y0[tid*2+1] = __floats2bfloat162_rn((x0.z-mu0)*rs0*wv.z + bv.z,
                                        (x0.w-mu0)*rs0*wv.w + bv.w);
    y1[tid*2]   = __floats2bfloat162_rn((x1.x-mu1)*rs1*wv.x + bv.x,
                                        (x1.y-mu1)*rs1*wv.y + bv.y);
    y1[tid*2+1] = __floats2bfloat162_rn((x1.z-mu1)*rs1*wv.z + bv.z,
                                        (x1.w-mu1)*rs1*wv.w + bv.w);
}

// ------- per-expert exact top-k: per-warp histograms + parallel tie rank ---
#define TPK_T 1024
#define TPK_PER (BS_TOK / TPK_T)            // 16 keys per thread
#define TPK_SMEM (BS_TOK * 4 + 32 * 256 * 4) // 64KB keys + 32KB warp hists

__global__ __launch_bounds__(TPK_T, 1) void topk_kernel() {
    extern __shared__ unsigned sm[];
    unsigned* skeys = sm;                    // [BS_TOK]
    unsigned* whist = sm + BS_TOK;           // [32][256]
    __shared__ unsigned suf[256];
    __shared__ int scn[TPK_T];
    __shared__ unsigned s_prefix;
    __shared__ int s_need, s_out;

    const int e = blockIdx.x;
    const int tid = threadIdx.x, lane = tid & 31, wrp = tid >> 5;
    const unsigned* keys = g_keys + (size_t)e * BS_TOK;

#pragma unroll
    for (int i = 0; i < BS_TOK / (TPK_T * 4); i++) {
        uint4 v = ((const uint4*)keys)[tid + i * TPK_T];
        ((uint4*)skeys)[tid + i * TPK_T] = v;
    }
    if (tid == 0) { s_prefix = 0u; s_need = KCAP; s_out = 0; }
    __syncthreads();

    // 4 passes, 8 bits each (MSB first)
#pragma unroll
    for (int p = 3; p >= 0; p--) {
#pragma unroll
        for (int i = 0; i < 8; i++) whist[tid + i * TPK_T] = 0u;
        __syncthreads();
        const int sh = p * 8;
        const unsigned maskHi = (p == 3) ? 0u : (0xFFFFFFFFu << ((p + 1) * 8));
        const unsigned pref = s_prefix;
        const int need = s_need;
        unsigned* myh = whist + wrp * 256;
#pragma unroll
        for (int i = 0; i < TPK_PER; i++) {
            unsigned k = skeys[tid + i * TPK_T];
            bool m = ((k & maskHi) == pref);
            unsigned bin = m ? ((k >> sh) & 255u) : 0xFFFFFFFFu;
            unsigned peers = __match_any_sync(0xffffffffu, bin);
            // leader per distinct bin -> conflict-free non-atomic add
            if (m && lane == (__ffs(peers) - 1))
                myh[bin] += (unsigned)__popc(peers);
        }
        __syncthreads();
        // fold 32 warp hists + suffix scan over 256 bins
        if (tid < 256) {
            unsigned s = 0;
#pragma unroll
            for (int w2 = 0; w2 < 32; w2++) s += whist[w2 * 256 + tid];
            suf[tid] = s;
        }
        __syncthreads();
#pragma unroll
        for (int st = 1; st < 256; st <<= 1) {
            unsigned v = 0;
            if (tid < 256) v = suf[tid] + ((tid + st < 256) ? suf[tid + st] : 0u);
            __syncthreads();
            if (tid < 256) suf[tid] = v;
            __syncthreads();
        }
        if (tid < 256) {
            unsigned nxt = (tid == 255) ? 0u : suf[tid + 1];
            if ((int)suf[tid] >= need && (int)nxt < need) {
                s_prefix = pref | ((unsigned)tid << sh);
                s_need = need - (int)nxt;
            }
        }
        __syncthreads();
    }

    const unsigned T = s_prefix;
    const int needEq = s_need;

    // blocked partition: thread owns TPK_PER consecutive keys; parallel rank
    const int base = tid * TPK_PER;
    int cnt = 0;
#pragma unroll
    for (int j = 0; j < TPK_PER; j++) cnt += (skeys[base + j] == T);
    scn[tid] = cnt;
    __syncthreads();
#pragma unroll
    for (int st = 1; st < TPK_T; st <<= 1) {
        int v = (tid >= st) ? scn[tid - st] : 0;
        __syncthreads();
        scn[tid] += v;
        __syncthreads();
    }
    int r = scn[tid] - cnt;                  // exclusive rank base
#pragma unroll
    for (int j = 0; j < TPK_PER; j++) {
        int t = base + j;
        unsigned k = skeys[t];
        bool sel;
        if (k > T) sel = true;
        else if (k == T) { sel = (r < needEq); r++; }
        else sel = false;
        if (sel) {
            int slot = atomicAdd(&s_out, 1);
            g_selidx[e * KCAP + slot] = t;
            g_selw  [e * KCAP + slot] = g_scores[(size_t)e * BS_TOK + t];
            g_t2s[t * NEXP + e] = e * KCAP + slot;
        }
    }
}

// ---------------- mma.sync GEMM: 128x256x64 tiles, 4-stage cp.async --------
#define BM 128
#define BN 256
#define BK 64
#define NSTG 4
#define STGB ((BM + BN) * BK * 2)     // 49152 bytes per stage
#define GEMM_SMEM (NSTG * STGB)       // 196608

__device__ __forceinline__ float gelu_f(float v) {
    float u = 0.7978845608028654f * (v + 0.044715f * v * v * v);
    float e = __expf(2.f * u);
    float th = 1.f - __fdividef(2.f, e + 1.f);
    return 0.5f * v * (1.f + th);
}

// EPI==1: g_H = gelu(LN(x)[tok] @ W1^T + b1) bf16.  EPI==2: g_O[slot]=(acc+b2)*w
template <int EPI, int M, int N, int K>
__global__ __launch_bounds__(256, 1) void mma_gemm(const float* __restrict__ bias) {
    extern __shared__ __align__(1024) char smdyn[];
    const int tid = threadIdx.x, wid = tid >> 5, lane = tid & 31;
    const int wm = wid >> 2, wn = wid & 3;           // 2 x 4 warps, 64x64 tiles
    const int e = blockIdx.z;
    uint32_t sb = smem_u32(smdyn);

    const int GX = N / BN;
    int lin = blockIdx.y * GX + blockIdx.x;
    int bm, bn;
    {
        int inb = lin % (8 * GX);
        int g2 = lin / (8 * GX);
        bm = g2 * 8 + (inb & 7);
        bn = inb >> 3;
    }

    const __nv_bfloat16* B = ((EPI == 1) ? g_w1 : g_w2) +
                             ((size_t)e * N + (size_t)bn * BN) * (size_t)K;
    const __nv_bfloat16* A2 = g_H + ((size_t)e * M + (size_t)bm * BM) * (size_t)K;

    __shared__ float bsm[BN];
    __shared__ int stok[BM];          // slot -> token map (EPI==1 gather)
    bsm[tid] = bias[(size_t)e * N + bn * BN + tid];
    if (EPI == 1 && tid < BM) stok[tid] = g_selidx[e * KCAP + bm * BM + tid];
    __syncthreads();

    auto fill = [&](int c, int s) {
        uint32_t abase = sb + s * STGB;
        uint32_t bbase = abase + BM * BK * 2;     // +16KB
        const __nv_bfloat16* gb = B + c * BK;
#pragma unroll
        for (int t = 0; t < 4; t++) {
            int i = tid + t * 256;
            int row = i >> 3, seg = i & 7;
            uint32_t off = (uint32_t)(row * 128 + seg * 16);
            off ^= (off >> 3) & 0x70u;
            const __nv_bfloat16* ga;
            if (EPI == 1)
                ga = g_xln + (size_t)stok[row] * K + c * BK + seg * 8;
            else
                ga = A2 + (size_t)row * K + c * BK + seg * 8;
            asm volatile("cp.async.cg.shared.global [%0], [%1], 16;"
                         :: "r"(abase + off), "l"(ga));
        }
#pragma unroll
        for (int t = 0; t < 8; t++) {
            int i = tid + t * 256;
            int row = i >> 3, seg = i & 7;
            uint32_t off = (uint32_t)(row * 128 + seg * 16);
            off ^= (off >> 3) & 0x70u;
            asm volatile("cp.async.cg.shared.global [%0], [%1], 16;"
                         :: "r"(bbase + off), "l"(gb + (size_t)row * K + seg * 8));
        }
        asm volatile("cp.async.commit_group;" ::: "memory");
    };

    float c[4][8][4];
#pragma unroll
    for (int a = 0; a < 4; a++)
#pragma unroll
        for (int b = 0; b < 8; b++)
#pragma unroll
            for (int d = 0; d < 4; d++) c[a][b][d] = 0.f;

    const int nk = K / BK;
    fill(0, 0); fill(1, 1); fill(2, 2);

    for (int kc = 0; kc < nk; kc++) {
        int rem = nk - 1 - kc;
        if (rem >= 2) cp_wait<2>();
        else if (rem == 1) cp_wait<1>();
        else cp_wait<0>();
        __syncthreads();
        if (kc + 3 < nk) fill(kc + 3, (kc + 3) & 3);

        uint32_t abase = sb + (kc & 3) * STGB;
        uint32_t bbase = abase + BM * BK * 2;

#pragma unroll
        for (int ks = 0; ks < 4; ks++) {
            uint32_t a[4][4], b[8][2];
            int ar = wm * 64 + (lane & 15);
            int ac = ks * 32 + (lane >> 4) * 16;
#pragma unroll
            for (int mi = 0; mi < 4; mi++) {
                uint32_t off = (uint32_t)((ar + mi * 16) * 128 + ac);
                off ^= (off >> 3) & 0x70u;
                asm volatile(
                    "ldmatrix.sync.aligned.m8n8.x4.shared.b16 {%0,%1,%2,%3}, [%4];"
                    : "=r"(a[mi][0]), "=r"(a[mi][1]), "=r"(a[mi][2]), "=r"(a[mi][3])
                    : "r"(abase + off));
            }
            int nr = wn * 64 + (lane & 7) + ((lane >> 4) << 3);
            int kb = ks * 32 + ((lane >> 3) & 1) * 16;
#pragma unroll
            for (int nb = 0; nb < 4; nb++) {
                uint32_t off = (uint32_t)((nr + nb * 16) * 128 + kb);
                off ^= (off >> 3) & 0x70u;
                asm volatile(
                    "ldmatrix.sync.aligned.m8n8.x4.shared.b16 {%0,%1,%2,%3}, [%4];"
                    : "=r"(b[2*nb][0]), "=r"(b[2*nb][1]),
                      "=r"(b[2*nb+1][0]), "=r"(b[2*nb+1][1])
                    : "r"(bbase + off));
            }
#pragma unroll
            for (int mi = 0; mi < 4; mi++)
#pragma unroll
                for (int ni = 0; ni < 8; ni++) {
                    asm volatile(
                        "mma.sync.aligned.m16n8k16.row.col.f32.bf16.bf16.f32 "
                        "{%0,%1,%2,%3}, {%4,%5,%6,%7}, {%8,%9}, {%0,%1,%2,%3};"
                        : "+f"(c[mi][ni][0]), "+f"(c[mi][ni][1]),
                          "+f"(c[mi][ni][2]), "+f"(c[mi][ni][3])
                        : "r"(a[mi][0]), "r"(a[mi][1]), "r"(a[mi][2]), "r"(a[mi][3]),
                          "r"(b[ni][0]), "r"(b[ni][1]));
                }
        }
        __syncthreads();
    }

    // -------- epilogue --------
    int g4 = lane >> 2, tg2 = (lane & 3) * 2;
    if (EPI == 1) {
#pragma unroll
        for (int mi = 0; mi < 4; mi++) {
            int row = bm * BM + wm * 64 + mi * 16 + g4;
            size_t h0 = ((size_t)e * M + row) * (size_t)N;
            size_t h1 = ((size_t)e * M + row + 8) * (size_t)N;
#pragma unroll
            for (int ni = 0; ni < 8; ni++) {
                int lc = wn * 64 + ni * 8 + tg2;
                int col = bn * BN + lc;
                float bb0 = bsm[lc], bb1 = bsm[lc + 1];
                *(__nv_bfloat162*)(g_H + h0 + col) = __floats2bfloat162_rn(
                    gelu_f(c[mi][ni][0] + bb0), gelu_f(c[mi][ni][1] + bb1));
                *(__nv_bfloat162*)(g_H + h1 + col) = __floats2bfloat162_rn(
                    gelu_f(c[mi][ni][2] + bb0), gelu_f(c[mi][ni][3] + bb1));
            }
        }
    } else {
#pragma unroll
        for (int mi = 0; mi < 4; mi++) {
            int row = bm * BM + wm * 64 + mi * 16 + g4;
            float w0 = g_selw[e * KCAP + row];
            float w1 = g_selw[e * KCAP + row + 8];
            size_t o0 = ((size_t)e * M + row) * (size_t)N;
            size_t o1 = ((size_t)e * M + row + 8) * (size_t)N;
#pragma unroll
            for (int ni = 0; ni < 8; ni++) {
                int lc = wn * 64 + ni * 8 + tg2;
                int col = bn * BN + lc;
                float bb0 = bsm[lc], bb1 = bsm[lc + 1];
                float2 v0 = make_float2((c[mi][ni][0] + bb0) * w0,
                                        (c[mi][ni][1] + bb1) * w0);
                float2 v1 = make_float2((c[mi][ni][2] + bb0) * w1,
                                        (c[mi][ni][3] + bb1) * w1);
                *(float2*)(g_O + o0 + col) = v0;
                *(float2*)(g_O + o1 + col) = v1;
            }
        }
    }
}

// ---------------- final combine (2 tokens/block) ---------------------------
__global__ void combine_kernel(const float* __restrict__ x,
                               float* __restrict__ out) {
    int t0 = blockIdx.x * 2;
    int t1 = t0 + 1;
    int j = threadIdx.x;
    __shared__ int sl[2][NEXP];
    if (j < NEXP) sl[0][j] = g_t2s[t0 * NEXP + j];
    else if (j < 2 * NEXP) sl[1][j - NEXP] = g_t2s[t1 * NEXP + (j - NEXP)];
    float4 a0 = ((const float4*)(x + (size_t)t0 * DIM))[j];
    float4 a1 = ((const float4*)(x + (size_t)t1 * DIM))[j];
    __syncthreads();
#pragma unroll
    for (int e = 0; e < NEXP; e++) {
        int s0 = sl[0][e], s1 = sl[1][e];
        if (s0 >= 0) {
            float4 o = ((const float4*)(g_O + (size_t)s0 * DIM))[j];
            a0.x += o.x; a0.y += o.y; a0.z += o.z; a0.w += o.w;
        }
        if (s1 >= 0) {
            float4 o = ((const float4*)(g_O + (size_t)s1 * DIM))[j];
            a1.x += o.x; a1.y += o.y; a1.z += o.z; a1.w += o.w;
        }
    }
    ((float4*)(out + (size_t)t0 * DIM))[j] = a0;
    ((float4*)(out + (size_t)t1 * DIM))[j] = a1;
}

// ---------------- launch ---------------------------------------------------
extern "C" void kernel_launch(void* const* d_in, const int* in_sizes, int n_in,
                              void* d_out, int out_size) {
    const float* x   = (const float*)d_in[0];
    const float* gw  = (const float*)d_in[1];
    const float* lnw = (const float*)d_in[2];
    const float* lnb = (const float*)d_in[3];
    const float* fc1 = (const float*)d_in[4];
    const float* b1  = (const float*)d_in[5];
    const float* fc2 = (const float*)d_in[6];
    const float* b2  = (const float*)d_in[7];
    float* out = (float*)d_out;

    cudaFuncSetAttribute(mma_gemm<1, KCAP, DDIM, DIM>,
                         cudaFuncAttributeMaxDynamicSharedMemorySize, GEMM_SMEM);
    cudaFuncSetAttribute(mma_gemm<2, KCAP, DIM, DDIM>,
                         cudaFuncAttributeMaxDynamicSharedMemorySize, GEMM_SMEM);
    cudaFuncSetAttribute(topk_kernel,
                         cudaFuncAttributeMaxDynamicSharedMemorySize, TPK_SMEM);

    // fork: side stream converts w1 (joins GEMM1) then w2 (joins GEMM2,
    // hidden under GEMM1). Main stream: gate_ln -> topk.
    cudaStream_t sB;
    cudaStreamCreateWithFlags(&sB, cudaStreamNonBlocking);
    cudaEvent_t evFork, evW1, evW2;
    cudaEventCreateWithFlags(&evFork, cudaEventDisableTiming);
    cudaEventCreateWithFlags(&evW1,   cudaEventDisableTiming);
    cudaEventCreateWithFlags(&evW2,   cudaEventDisableTiming);

    cudaEventRecord(evFork, 0);
    cudaStreamWaitEvent(sB, evFork, 0);
    convert_w_kernel<<<4096, 256, 0, sB>>>((const float4*)fc1, 1);
    cudaEventRecord(evW1, sB);
    convert_w_kernel<<<4096, 256, 0, sB>>>((const float4*)fc2, 2);
    cudaEventRecord(evW2, sB);

    gate_ln_kernel<<<BS_TOK / 2, 256>>>(x, gw, lnw, lnb);  // scores + x_ln + t2s init
    topk_kernel<<<NEXP, TPK_T, TPK_SMEM>>>();

    cudaStreamWaitEvent(0, evW1, 0);                  // w1 ready
    {   // GEMM1: per expert (2048 x 4096 x 1024), A gathered from x_ln
        dim3 grid(DDIM / BN, KCAP / BM, NEXP);   // (16, 16, 8)
        mma_gemm<1, KCAP, DDIM, DIM><<<grid, 256, GEMM_SMEM>>>(b1);
    }
    cudaStreamWaitEvent(0, evW2, 0);                  // w2 ready
    {   // GEMM2: per expert (2048 x 1024 x 4096), bias + gate scale -> g_O
        dim3 grid(DIM / BN, KCAP / BM, NEXP);    // (4, 16, 8)
        mma_gemm<2, KCAP, DIM, DDIM><<<grid, 256, GEMM_SMEM>>>(b2);
    }
    combine_kernel<<<BS_TOK / 2, 256>>>(x, out);
}

// round 13
// speedup vs baseline: 1.0922x; 1.0020x over previous
#include <cuda_runtime.h>
#include <cuda_bf16.h>
#include <math.h>
#include <stdint.h>

#define BS_TOK 16384
#define DIM    1024
#define DDIM   4096
#define NEXP   8
#define KCAP   2048   // tokens per expert

// ---------------- scratch (device globals; allocation-free rule) ----------
__device__ __align__(16) __nv_bfloat16 g_w1 [(size_t)NEXP * DDIM * DIM]; // 64MB
__device__ __align__(16) __nv_bfloat16 g_w2 [(size_t)NEXP * DIM * DDIM]; // 64MB
__device__ __align__(16) __nv_bfloat16 g_xln[(size_t)BS_TOK * DIM];      // 32MB (token-ordered LN(x))
__device__ __align__(16) __nv_bfloat16 g_H  [(size_t)BS_TOK * DDIM];    // 128MB
__device__ __align__(16) float g_O[(size_t)BS_TOK * DIM];                // 64MB
__device__ float    g_scores[NEXP * BS_TOK];
__device__ unsigned g_keys  [NEXP * BS_TOK];
__device__ int      g_selidx[BS_TOK];
__device__ float    g_selw  [BS_TOK];
__device__ int      g_t2s   [BS_TOK * NEXP];   // token -> slot (or -1)

// ---------------- small helpers -------------------------------------------
__device__ __forceinline__ uint32_t smem_u32(const void* p) {
    uint32_t a;
    asm("{ .reg .u64 t; cvta.to.shared.u64 t, %1; cvt.u32.u64 %0, t; }"
        : "=r"(a) : "l"(p));
    return a;
}
template <int N>
__device__ __forceinline__ void cp_wait() {
    asm volatile("cp.async.wait_group %0;" :: "n"(N) : "memory");
}

// ---------------- weight conversion fp32 -> bf16 (one matrix) -------------
__global__ void convert_w_kernel(const float4* __restrict__ src, int which) {
    size_t n = (size_t)NEXP * DDIM * DIM / 4;
    __nv_bfloat162* dst = (which == 1) ? (__nv_bfloat162*)g_w1
                                       : (__nv_bfloat162*)g_w2;
    for (size_t i = (size_t)blockIdx.x * blockDim.x + threadIdx.x; i < n;
         i += (size_t)gridDim.x * blockDim.x) {
        float4 a = src[i];
        dst[2*i]   = __floats2bfloat162_rn(a.x, a.y);
        dst[2*i+1] = __floats2bfloat162_rn(a.z, a.w);
    }
}

// -------- gating + LayerNorm fused: softmax scores + x_ln, 2 tok/block -----
__global__ void gate_ln_kernel(const float* __restrict__ x,
                               const float* __restrict__ gw,
                               const float* __restrict__ lnw,
                               const float* __restrict__ lnb) {
    int t0 = blockIdx.x * 2;
    int tid = threadIdx.x;
    if (tid < 2 * NEXP) g_t2s[t0 * NEXP + tid] = -1;   // fold t2s init
    const float4 x0 = ((const float4*)(x + (size_t)t0 * DIM))[tid];
    const float4 x1 = ((const float4*)(x + (size_t)(t0 + 1) * DIM))[tid];
    float a0[NEXP], a1[NEXP];
#pragma unroll
    for (int e = 0; e < NEXP; e++) {
        float4 wv = ((const float4*)(gw + (size_t)e * DIM))[tid];
        a0[e] = x0.x*wv.x + x0.y*wv.y + x0.z*wv.z + x0.w*wv.w;
        a1[e] = x1.x*wv.x + x1.y*wv.y + x1.z*wv.z + x1.w*wv.w;
    }
    float s0 = x0.x + x0.y + x0.z + x0.w;
    float q0 = x0.x*x0.x + x0.y*x0.y + x0.z*x0.z + x0.w*x0.w;
    float s1 = x1.x + x1.y + x1.z + x1.w;
    float q1 = x1.x*x1.x + x1.y*x1.y + x1.z*x1.z + x1.w*x1.w;
#pragma unroll
    for (int o = 16; o > 0; o >>= 1) {
#pragma unroll
        for (int e = 0; e < NEXP; e++) {
            a0[e] += __shfl_xor_sync(0xffffffffu, a0[e], o);
            a1[e] += __shfl_xor_sync(0xffffffffu, a1[e], o);
        }
        s0 += __shfl_xor_sync(0xffffffffu, s0, o);
        q0 += __shfl_xor_sync(0xffffffffu, q0, o);
        s1 += __shfl_xor_sync(0xffffffffu, s1, o);
        q1 += __shfl_xor_sync(0xffffffffu, q1, o);
    }

    __shared__ float sh[2][8][NEXP];
    __shared__ float red[4][8];
    __shared__ float lg[2][NEXP];
    __shared__ float fin[4];
    int w = tid >> 5, l = tid & 31;
    if (l == 0) {
#pragma unroll
        for (int e = 0; e < NEXP; e++) { sh[0][w][e] = a0[e]; sh[1][w][e] = a1[e]; }
        red[0][w] = s0; red[1][w] = q0; red[2][w] = s1; red[3][w] = q1;
    }
    __syncthreads();
    if (tid < 16) {
        int tk = tid >> 3, e = tid & 7;
        float s = 0.f;
#pragma unroll
        for (int i = 0; i < 8; i++) s += sh[tk][i][e];
        lg[tk][e] = s;
    }
    if (tid >= 32 && tid < 34) {
        int tk = tid - 32;
        float S = 0.f, Q = 0.f;
#pragma unroll
        for (int i = 0; i < 8; i++) { S += red[2*tk][i]; Q += red[2*tk+1][i]; }
        float mu = S * (1.f / DIM);
        float var = Q * (1.f / DIM) - mu * mu;
        fin[2*tk]   = mu;
        fin[2*tk+1] = rsqrtf(var + 1e-5f);
    }
    __syncthreads();
    if (tid < 16) {
        int tk = tid >> 3, e = tid & 7;
        int t = t0 + tk;
        float mx = lg[tk][0];
#pragma unroll
        for (int i = 1; i < NEXP; i++) mx = fmaxf(mx, lg[tk][i]);
        float den = 0.f;
#pragma unroll
        for (int i = 0; i < NEXP; i++) den += expf(lg[tk][i] - mx);
        float sc = expf(lg[tk][e] - mx) / den;
        g_scores[e * BS_TOK + t] = sc;
        unsigned b = __float_as_uint(sc);
        b ^= (b >> 31) ? 0xFFFFFFFFu : 0x80000000u;
        g_keys[e * BS_TOK + t] = b;
    }
    float mu0 = fin[0], rs0 = fin[1], mu1 = fin[2], rs1 = fin[3];
    float4 wv = ((const float4*)lnw)[tid];
    float4 bv = ((const float4*)lnb)[tid];
    __nv_bfloat162* y0 = (__nv_bfloat162*)(g_xln + (size_t)t0 * DIM);
    __nv_bfloat162* y1 = (__nv_bfloat162*)(g_xln + (size_t)(t0 + 1) * DIM);
    y0[tid*2]   = __floats2bfloat162_rn((x0.x-mu0)*rs0*wv.x + bv.x,
                                        (x0.y-mu0)*rs0*wv.y + bv.y);
    y0[tid*2+1] = __floats2bfloat162_rn((x0.z-mu0)*rs0*wv.z + bv.z,
                                        (x0.w-mu0)*rs0*wv.w + bv.w);
    y1[tid*2]   = __floats2bfloat162_rn((x1.x-mu1)*rs1*wv.x + bv.x,
                                        (x1.y-mu1)*rs1*wv.y + bv.y);
    y1[tid*2+1] = __floats2bfloat162_rn((x1.z-mu1)*rs1*wv.z + bv.z,
                                        (x1.w-mu1)*rs1*wv.w + bv.w);
}

// ------- per-expert exact top-k: warp hists + shuffle scans (few barriers) -
#define TPK_T 1024
#define TPK_PER (BS_TOK / TPK_T)            // 16 keys per thread
#define TPK_SMEM (BS_TOK * 4 + 32 * 256 * 4) // 64KB keys + 32KB warp hists

__global__ __launch_bounds__(TPK_T, 1) void topk_kernel() {
    extern __shared__ unsigned sm[];
    unsigned* skeys = sm;                    // [BS_TOK]
    unsigned* whist = sm + BS_TOK;           // [32][256]
    __shared__ unsigned suf[256];
    __shared__ int wsum[32];
    __shared__ unsigned s_prefix;
    __shared__ int s_need, s_out;

    const int e = blockIdx.x;
    const int tid = threadIdx.x, lane = tid & 31, wrp = tid >> 5;
    const unsigned* keys = g_keys + (size_t)e * BS_TOK;

#pragma unroll
    for (int i = 0; i < BS_TOK / (TPK_T * 4); i++) {
        uint4 v = ((const uint4*)keys)[tid + i * TPK_T];
        ((uint4*)skeys)[tid + i * TPK_T] = v;
    }
    if (tid == 0) { s_prefix = 0u; s_need = KCAP; s_out = 0; }
    __syncthreads();

    // 4 passes, 8 bits each (MSB first)
#pragma unroll
    for (int p = 3; p >= 0; p--) {
#pragma unroll
        for (int i = 0; i < 8; i++) whist[tid + i * TPK_T] = 0u;
        __syncthreads();
        const int sh = p * 8;
        const unsigned maskHi = (p == 3) ? 0u : (0xFFFFFFFFu << ((p + 1) * 8));
        const unsigned pref = s_prefix;
        const int need = s_need;
        unsigned* myh = whist + wrp * 256;
#pragma unroll
        for (int i = 0; i < TPK_PER; i++) {
            unsigned k = skeys[tid + i * TPK_T];
            bool m = ((k & maskHi) == pref);
            unsigned bin = m ? ((k >> sh) & 255u) : 0xFFFFFFFFu;
            unsigned peers = __match_any_sync(0xffffffffu, bin);
            if (m && lane == (__ffs(peers) - 1))
                myh[bin] += (unsigned)__popc(peers);
        }
        __syncthreads();
        // fold 32 warp hists into suf (raw counts)
        if (tid < 256) {
            unsigned s = 0;
#pragma unroll
            for (int w2 = 0; w2 < 32; w2++) s += whist[w2 * 256 + tid];
            suf[tid] = s;
        }
        __syncthreads();
        // single-warp suffix scan: lane owns 8 bins in registers
        if (wrp == 0) {
            unsigned v[8];
            unsigned tot = 0;
#pragma unroll
            for (int j = 0; j < 8; j++) { v[j] = suf[lane * 8 + j]; tot += v[j]; }
            // suffix sum over lanes (sum of tot for lanes >= lane)
            unsigned s = tot;
#pragma unroll
            for (int o = 1; o < 32; o <<= 1) {
                unsigned t = __shfl_down_sync(0xffffffffu, s, o);
                if (lane + o < 32) s += t;
            }
            unsigned acc = s - tot;          // sum over lanes > lane
#pragma unroll
            for (int j = 7; j >= 0; j--) { acc += v[j]; v[j] = acc; }
#pragma unroll
            for (int j = 0; j < 8; j++) suf[lane * 8 + j] = v[j];
        }
        __syncthreads();
        if (tid < 256) {
            unsigned nxt = (tid == 255) ? 0u : suf[tid + 1];
            if ((int)suf[tid] >= need && (int)nxt < need) {
                s_prefix = pref | ((unsigned)tid << sh);
                s_need = need - (int)nxt;
            }
        }
        __syncthreads();
    }

    const unsigned T = s_prefix;
    const int needEq = s_need;

    // blocked partition + shuffle-hierarchical rank scan (2 barriers)
    const int base = tid * TPK_PER;
    int cnt = 0;
#pragma unroll
    for (int j = 0; j < TPK_PER; j++) cnt += (skeys[base + j] == T);
    int inc = cnt;
#pragma unroll
    for (int o = 1; o < 32; o <<= 1) {
        int t = __shfl_up_sync(0xffffffffu, inc, o);
        if (lane >= o) inc += t;
    }
    if (lane == 31) wsum[wrp] = inc;
    __syncthreads();
    if (tid < 32) {
        int v = wsum[tid];
        int sc = v;
#pragma unroll
        for (int o = 1; o < 32; o <<= 1) {
            int t = __shfl_up_sync(0xffffffffu, sc, o);
            if (lane >= o) sc += t;
        }
        wsum[tid] = sc - v;                  // exclusive warp base
    }
    __syncthreads();
    int r = wsum[wrp] + inc - cnt;           // exclusive rank base
#pragma unroll
    for (int j = 0; j < TPK_PER; j++) {
        int t = base + j;
        unsigned k = skeys[t];
        bool sel;
        if (k > T) sel = true;
        else if (k == T) { sel = (r < needEq); r++; }
        else sel = false;
        if (sel) {
            int slot = atomicAdd(&s_out, 1);
            g_selidx[e * KCAP + slot] = t;
            g_selw  [e * KCAP + slot] = g_scores[(size_t)e * BS_TOK + t];
            g_t2s[t * NEXP + e] = e * KCAP + slot;
        }
    }
}

// ---------------- mma.sync GEMM: 128x256x64 tiles, 4-stage cp.async --------
#define BM 128
#define BN 256
#define BK 64
#define NSTG 4
#define STGB ((BM + BN) * BK * 2)     // 49152 bytes per stage
#define GEMM_SMEM (NSTG * STGB)       // 196608

__device__ __forceinline__ float gelu_f(float v) {
    float u = 0.7978845608028654f * (v + 0.044715f * v * v * v);
    float e = __expf(2.f * u);
    float th = 1.f - __fdividef(2.f, e + 1.f);
    return 0.5f * v * (1.f + th);
}

// EPI==1: g_H = gelu(LN(x)[tok] @ W1^T + b1) bf16.  EPI==2: g_O[slot]=(acc+b2)*w
template <int EPI, int M, int N, int K>
__global__ __launch_bounds__(256, 1) void mma_gemm(const float* __restrict__ bias) {
    extern __shared__ __align__(1024) char smdyn[];
    const int tid = threadIdx.x, wid = tid >> 5, lane = tid & 31;
    const int wm = wid >> 2, wn = wid & 3;           // 2 x 4 warps, 64x64 tiles
    const int e = blockIdx.z;
    uint32_t sb = smem_u32(smdyn);

    const int GX = N / BN;
    int lin = blockIdx.y * GX + blockIdx.x;
    int bm, bn;
    {
        int inb = lin % (8 * GX);
        int g2 = lin / (8 * GX);
        bm = g2 * 8 + (inb & 7);
        bn = inb >> 3;
    }

    const __nv_bfloat16* B = ((EPI == 1) ? g_w1 : g_w2) +
                             ((size_t)e * N + (size_t)bn * BN) * (size_t)K;
    const __nv_bfloat16* A2 = g_H + ((size_t)e * M + (size_t)bm * BM) * (size_t)K;

    __shared__ float bsm[BN];
    __shared__ int stok[BM];          // slot -> token map (EPI==1 gather)
    bsm[tid] = bias[(size_t)e * N + bn * BN + tid];
    if (EPI == 1 && tid < BM) stok[tid] = g_selidx[e * KCAP + bm * BM + tid];
    __syncthreads();

    auto fill = [&](int c, int s) {
        uint32_t abase = sb + s * STGB;
        uint32_t bbase = abase + BM * BK * 2;     // +16KB
        const __nv_bfloat16* gb = B + c * BK;
#pragma unroll
        for (int t = 0; t < 4; t++) {
            int i = tid + t * 256;
            int row = i >> 3, seg = i & 7;
            uint32_t off = (uint32_t)(row * 128 + seg * 16);
            off ^= (off >> 3) & 0x70u;
            const __nv_bfloat16* ga;
            if (EPI == 1)
                ga = g_xln + (size_t)stok[row] * K + c * BK + seg * 8;
            else
                ga = A2 + (size_t)row * K + c * BK + seg * 8;
            asm volatile("cp.async.cg.shared.global [%0], [%1], 16;"
                         :: "r"(abase + off), "l"(ga));
        }
#pragma unroll
        for (int t = 0; t < 8; t++) {
            int i = tid + t * 256;
            int row = i >> 3, seg = i & 7;
            uint32_t off = (uint32_t)(row * 128 + seg * 16);
            off ^= (off >> 3) & 0x70u;
            asm volatile("cp.async.cg.shared.global [%0], [%1], 16;"
                         :: "r"(bbase + off), "l"(gb + (size_t)row * K + seg * 8));
        }
        asm volatile("cp.async.commit_group;" ::: "memory");
    };

    float c[4][8][4];
#pragma unroll
    for (int a = 0; a < 4; a++)
#pragma unroll
        for (int b = 0; b < 8; b++)
#pragma unroll
            for (int d = 0; d < 4; d++) c[a][b][d] = 0.f;

    const int nk = K / BK;
    fill(0, 0); fill(1, 1); fill(2, 2);

    for (int kc = 0; kc < nk; kc++) {
        int rem = nk - 1 - kc;
        if (rem >= 2) cp_wait<2>();
        else if (rem == 1) cp_wait<1>();
        else cp_wait<0>();
        __syncthreads();
        if (kc + 3 < nk) fill(kc + 3, (kc + 3) & 3);

        uint32_t abase = sb + (kc & 3) * STGB;
        uint32_t bbase = abase + BM * BK * 2;

#pragma unroll
        for (int ks = 0; ks < 4; ks++) {
            uint32_t a[4][4], b[8][2];
            int ar = wm * 64 + (lane & 15);
            int ac = ks * 32 + (lane >> 4) * 16;
#pragma unroll
            for (int mi = 0; mi < 4; mi++) {
                uint32_t off = (uint32_t)((ar + mi * 16) * 128 + ac);
                off ^= (off >> 3) & 0x70u;
                asm volatile(
                    "ldmatrix.sync.aligned.m8n8.x4.shared.b16 {%0,%1,%2,%3}, [%4];"
                    : "=r"(a[mi][0]), "=r"(a[mi][1]), "=r"(a[mi][2]), "=r"(a[mi][3])
                    : "r"(abase + off));
            }
            int nr = wn * 64 + (lane & 7) + ((lane >> 4) << 3);
            int kb = ks * 32 + ((lane >> 3) & 1) * 16;
#pragma unroll
            for (int nb = 0; nb < 4; nb++) {
                uint32_t off = (uint32_t)((nr + nb * 16) * 128 + kb);
                off ^= (off >> 3) & 0x70u;
                asm volatile(
                    "ldmatrix.sync.aligned.m8n8.x4.shared.b16 {%0,%1,%2,%3}, [%4];"
                    : "=r"(b[2*nb][0]), "=r"(b[2*nb][1]),
                      "=r"(b[2*nb+1][0]), "=r"(b[2*nb+1][1])
                    : "r"(bbase + off));
            }
#pragma unroll
            for (int mi = 0; mi < 4; mi++)
#pragma unroll
                for (int ni = 0; ni < 8; ni++) {
                    asm volatile(
                        "mma.sync.aligned.m16n8k16.row.col.f32.bf16.bf16.f32 "
                        "{%0,%1,%2,%3}, {%4,%5,%6,%7}, {%8,%9}, {%0,%1,%2,%3};"
                        : "+f"(c[mi][ni][0]), "+f"(c[mi][ni][1]),
                          "+f"(c[mi][ni][2]), "+f"(c[mi][ni][3])
                        : "r"(a[mi][0]), "r"(a[mi][1]), "r"(a[mi][2]), "r"(a[mi][3]),
                          "r"(b[ni][0]), "r"(b[ni][1]));
                }
        }
        __syncthreads();
    }

    // -------- epilogue --------
    int g4 = lane >> 2, tg2 = (lane & 3) * 2;
    if (EPI == 1) {
#pragma unroll
        for (int mi = 0; mi < 4; mi++) {
            int row = bm * BM + wm * 64 + mi * 16 + g4;
            size_t h0 = ((size_t)e * M + row) * (size_t)N;
            size_t h1 = ((size_t)e * M + row + 8) * (size_t)N;
#pragma unroll
            for (int ni = 0; ni < 8; ni++) {
                int lc = wn * 64 + ni * 8 + tg2;
                int col = bn * BN + lc;
                float bb0 = bsm[lc], bb1 = bsm[lc + 1];
                *(__nv_bfloat162*)(g_H + h0 + col) = __floats2bfloat162_rn(
                    gelu_f(c[mi][ni][0] + bb0), gelu_f(c[mi][ni][1] + bb1));
                *(__nv_bfloat162*)(g_H + h1 + col) = __floats2bfloat162_rn(
                    gelu_f(c[mi][ni][2] + bb0), gelu_f(c[mi][ni][3] + bb1));
            }
        }
    } else {
#pragma unroll
        for (int mi = 0; mi < 4; mi++) {
            int row = bm * BM + wm * 64 + mi * 16 + g4;
            float w0 = g_selw[e * KCAP + row];
            float w1 = g_selw[e * KCAP + row + 8];
            size_t o0 = ((size_t)e * M + row) * (size_t)N;
            size_t o1 = ((size_t)e * M + row + 8) * (size_t)N;
#pragma unroll
            for (int ni = 0; ni < 8; ni++) {
                int lc = wn * 64 + ni * 8 + tg2;
                int col = bn * BN + lc;
                float bb0 = bsm[lc], bb1 = bsm[lc + 1];
                float2 v0 = make_float2((c[mi][ni][0] + bb0) * w0,
                                        (c[mi][ni][1] + bb1) * w0);
                float2 v1 = make_float2((c[mi][ni][2] + bb0) * w1,
                                        (c[mi][ni][3] + bb1) * w1);
                *(float2*)(g_O + o0 + col) = v0;
                *(float2*)(g_O + o1 + col) = v1;
            }
        }
    }
}

// ---------------- final combine (2 tokens/block) ---------------------------
__global__ void combine_kernel(const float* __restrict__ x,
                               float* __restrict__ out) {
    int t0 = blockIdx.x * 2;
    int t1 = t0 + 1;
    int j = threadIdx.x;
    __shared__ int sl[2][NEXP];
    if (j < NEXP) sl[0][j] = g_t2s[t0 * NEXP + j];
    else if (j < 2 * NEXP) sl[1][j - NEXP] = g_t2s[t1 * NEXP + (j - NEXP)];
    float4 a0 = ((const float4*)(x + (size_t)t0 * DIM))[j];
    float4 a1 = ((const float4*)(x + (size_t)t1 * DIM))[j];
    __syncthreads();
#pragma unroll
    for (int e = 0; e < NEXP; e++) {
        int s0 = sl[0][e], s1 = sl[1][e];
        if (s0 >= 0) {
            float4 o = ((const float4*)(g_O + (size_t)s0 * DIM))[j];
            a0.x += o.x; a0.y += o.y; a0.z += o.z; a0.w += o.w;
        }
        if (s1 >= 0) {
            float4 o = ((const float4*)(g_O + (size_t)s1 * DIM))[j];
            a1.x += o.x; a1.y += o.y; a1.z += o.z; a1.w += o.w;
        }
    }
    ((float4*)(out + (size_t)t0 * DIM))[j] = a0;
    ((float4*)(out + (size_t)t1 * DIM))[j] = a1;
}

// ---------------- launch ---------------------------------------------------
extern "C" void kernel_launch(void* const* d_in, const int* in_sizes, int n_in,
                              void* d_out, int out_size) {
    const float* x   = (const float*)d_in[0];
    const float* gw  = (const float*)d_in[1];
    const float* lnw = (const float*)d_in[2];
    const float* lnb = (const float*)d_in[3];
    const float* fc1 = (const float*)d_in[4];
    const float* b1  = (const float*)d_in[5];
    const float* fc2 = (const float*)d_in[6];
    const float* b2  = (const float*)d_in[7];
    float* out = (float*)d_out;

    cudaFuncSetAttribute(mma_gemm<1, KCAP, DDIM, DIM>,
                         cudaFuncAttributeMaxDynamicSharedMemorySize, GEMM_SMEM);
    cudaFuncSetAttribute(mma_gemm<2, KCAP, DIM, DDIM>,
                         cudaFuncAttributeMaxDynamicSharedMemorySize, GEMM_SMEM);
    cudaFuncSetAttribute(topk_kernel,
                         cudaFuncAttributeMaxDynamicSharedMemorySize, TPK_SMEM);

    // fork: side stream converts w1 (joins GEMM1) then w2 (joins GEMM2,
    // hidden under GEMM1). Main stream: gate_ln -> topk.
    cudaStream_t sB;
    cudaStreamCreateWithFlags(&sB, cudaStreamNonBlocking);
    cudaEvent_t evFork, evW1, evW2;
    cudaEventCreateWithFlags(&evFork, cudaEventDisableTiming);
    cudaEventCreateWithFlags(&evW1,   cudaEventDisableTiming);
    cudaEventCreateWithFlags(&evW2,   cudaEventDisableTiming);

    cudaEventRecord(evFork, 0);
    cudaStreamWaitEvent(sB, evFork, 0);
    convert_w_kernel<<<4096, 256, 0, sB>>>((const float4*)fc1, 1);
    cudaEventRecord(evW1, sB);
    convert_w_kernel<<<4096, 256, 0, sB>>>((const float4*)fc2, 2);
    cudaEventRecord(evW2, sB);

    gate_ln_kernel<<<BS_TOK / 2, 256>>>(x, gw, lnw, lnb);  // scores + x_ln + t2s init
    topk_kernel<<<NEXP, TPK_T, TPK_SMEM>>>();

    cudaStreamWaitEvent(0, evW1, 0);                  // w1 ready
    {   // GEMM1: per expert (2048 x 4096 x 1024), A gathered from x_ln
        dim3 grid(DDIM / BN, KCAP / BM, NEXP);   // (16, 16, 8)
        mma_gemm<1, KCAP, DDIM, DIM><<<grid, 256, GEMM_SMEM>>>(b1);
    }
    cudaStreamWaitEvent(0, evW2, 0);                  // w2 ready
    {   // GEMM2: per expert (2048 x 1024 x 4096), bias + gate scale -> g_O
        dim3 grid(DIM / BN, KCAP / BM, NEXP);    // (4, 16, 8)
        mma_gemm<2, KCAP, DIM, DDIM><<<grid, 256, GEMM_SMEM>>>(b2);
    }
    combine_kernel<<<BS_TOK / 2, 256>>>(x, out);
}

// round 14
// speedup vs baseline: 1.0966x; 1.0041x over previous
#include <cuda_runtime.h>
#include <cuda_bf16.h>
#include <math.h>
#include <stdint.h>

#define BS_TOK 16384
#define DIM    1024
#define DDIM   4096
#define NEXP   8
#define KCAP   2048   // tokens per expert

// ---------------- scratch (device globals; allocation-free rule) ----------
__device__ __align__(16) __nv_bfloat16 g_w1 [(size_t)NEXP * DDIM * DIM]; // 64MB
__device__ __align__(16) __nv_bfloat16 g_w2 [(size_t)NEXP * DIM * DDIM]; // 64MB
__device__ __align__(16) __nv_bfloat16 g_xln[(size_t)BS_TOK * DIM];      // 32MB (token-ordered LN(x))
__device__ __align__(16) __nv_bfloat16 g_H  [(size_t)BS_TOK * DDIM];    // 128MB
__device__ __align__(16) float g_O[(size_t)BS_TOK * DIM];                // 64MB
__device__ float    g_scores[NEXP * BS_TOK];
__device__ unsigned g_keys  [NEXP * BS_TOK];
__device__ int      g_selidx[BS_TOK];
__device__ float    g_selw  [BS_TOK];
__device__ int      g_t2s   [BS_TOK * NEXP];   // token -> slot (or -1)

// ---------------- small helpers -------------------------------------------
__device__ __forceinline__ uint32_t smem_u32(const void* p) {
    uint32_t a;
    asm("{ .reg .u64 t; cvta.to.shared.u64 t, %1; cvt.u32.u64 %0, t; }"
        : "=r"(a) : "l"(p));
    return a;
}
template <int N>
__device__ __forceinline__ void cp_wait() {
    asm volatile("cp.async.wait_group %0;" :: "n"(N) : "memory");
}

// ---------------- weight conversion fp32 -> bf16 (one matrix) -------------
__global__ void convert_w_kernel(const float4* __restrict__ src, int which) {
    size_t n = (size_t)NEXP * DDIM * DIM / 4;
    __nv_bfloat162* dst = (which == 1) ? (__nv_bfloat162*)g_w1
                                       : (__nv_bfloat162*)g_w2;
    for (size_t i = (size_t)blockIdx.x * blockDim.x + threadIdx.x; i < n;
         i += (size_t)gridDim.x * blockDim.x) {
        float4 a = src[i];
        dst[2*i]   = __floats2bfloat162_rn(a.x, a.y);
        dst[2*i+1] = __floats2bfloat162_rn(a.z, a.w);
    }
}

// -------- gating + LayerNorm fused: softmax scores + x_ln, 4 tok/block -----
__global__ void gate_ln_kernel(const float* __restrict__ x,
                               const float* __restrict__ gw,
                               const float* __restrict__ lnw,
                               const float* __restrict__ lnb) {
    int t0 = blockIdx.x * 4;
    int tid = threadIdx.x;
    if (tid < 4 * NEXP) g_t2s[t0 * NEXP + tid] = -1;   // fold t2s init
    float4 xv[4];
#pragma unroll
    for (int tk = 0; tk < 4; tk++)
        xv[tk] = ((const float4*)(x + (size_t)(t0 + tk) * DIM))[tid];
    float a[4][NEXP];
#pragma unroll
    for (int e = 0; e < NEXP; e++) {
        float4 wv = ((const float4*)(gw + (size_t)e * DIM))[tid];
#pragma unroll
        for (int tk = 0; tk < 4; tk++)
            a[tk][e] = xv[tk].x*wv.x + xv[tk].y*wv.y +
                       xv[tk].z*wv.z + xv[tk].w*wv.w;
    }
    float s[4], q[4];
#pragma unroll
    for (int tk = 0; tk < 4; tk++) {
        s[tk] = xv[tk].x + xv[tk].y + xv[tk].z + xv[tk].w;
        q[tk] = xv[tk].x*xv[tk].x + xv[tk].y*xv[tk].y +
                xv[tk].z*xv[tk].z + xv[tk].w*xv[tk].w;
    }
#pragma unroll
    for (int o = 16; o > 0; o >>= 1) {
#pragma unroll
        for (int tk = 0; tk < 4; tk++) {
#pragma unroll
            for (int e = 0; e < NEXP; e++)
                a[tk][e] += __shfl_xor_sync(0xffffffffu, a[tk][e], o);
            s[tk] += __shfl_xor_sync(0xffffffffu, s[tk], o);
            q[tk] += __shfl_xor_sync(0xffffffffu, q[tk], o);
        }
    }

    __shared__ float sh[4][8][NEXP];
    __shared__ float red[8][8];
    __shared__ float lg[4][NEXP];
    __shared__ float fin[8];
    int w = tid >> 5, l = tid & 31;
    if (l == 0) {
#pragma unroll
        for (int tk = 0; tk < 4; tk++) {
#pragma unroll
            for (int e = 0; e < NEXP; e++) sh[tk][w][e] = a[tk][e];
            red[2*tk][w] = s[tk]; red[2*tk+1][w] = q[tk];
        }
    }
    __syncthreads();
    if (tid < 32) {
        int tk = tid >> 3, e = tid & 7;
        float sv = 0.f;
#pragma unroll
        for (int i = 0; i < 8; i++) sv += sh[tk][i][e];
        lg[tk][e] = sv;
    }
    if (tid >= 32 && tid < 36) {
        int tk = tid - 32;
        float S = 0.f, Q = 0.f;
#pragma unroll
        for (int i = 0; i < 8; i++) { S += red[2*tk][i]; Q += red[2*tk+1][i]; }
        float mu = S * (1.f / DIM);
        float var = Q * (1.f / DIM) - mu * mu;
        fin[2*tk]   = mu;
        fin[2*tk+1] = rsqrtf(var + 1e-5f);
    }
    __syncthreads();
    if (tid < 32) {
        int tk = tid >> 3, e = tid & 7;
        int t = t0 + tk;
        float mx = lg[tk][0];
#pragma unroll
        for (int i = 1; i < NEXP; i++) mx = fmaxf(mx, lg[tk][i]);
        float den = 0.f;
#pragma unroll
        for (int i = 0; i < NEXP; i++) den += expf(lg[tk][i] - mx);
        float sc = expf(lg[tk][e] - mx) / den;
        g_scores[e * BS_TOK + t] = sc;
        unsigned b = __float_as_uint(sc);
        b ^= (b >> 31) ? 0xFFFFFFFFu : 0x80000000u;
        g_keys[e * BS_TOK + t] = b;
    }
    float4 wv = ((const float4*)lnw)[tid];
    float4 bv = ((const float4*)lnb)[tid];
#pragma unroll
    for (int tk = 0; tk < 4; tk++) {
        float mu = fin[2*tk], rs = fin[2*tk+1];
        __nv_bfloat162* y = (__nv_bfloat162*)(g_xln + (size_t)(t0 + tk) * DIM);
        y[tid*2]   = __floats2bfloat162_rn((xv[tk].x-mu)*rs*wv.x + bv.x,
                                           (xv[tk].y-mu)*rs*wv.y + bv.y);
        y[tid*2+1] = __floats2bfloat162_rn((xv[tk].z-mu)*rs*wv.z + bv.z,
                                           (xv[tk].w-mu)*rs*wv.w + bv.w);
    }
}

// ------- per-expert exact top-k: warp hists + shuffle scans, uint4 LDS -----
#define TPK_T 1024
#define TPK_PER (BS_TOK / TPK_T)            // 16 keys per thread
#define TPK_SMEM (BS_TOK * 4 + 32 * 256 * 4) // 64KB keys + 32KB warp hists

__global__ __launch_bounds__(TPK_T, 1) void topk_kernel() {
    extern __shared__ unsigned sm[];
    unsigned* skeys = sm;                    // [BS_TOK]
    unsigned* whist = sm + BS_TOK;           // [32][256]
    __shared__ unsigned suf[256];
    __shared__ int wsum[32];
    __shared__ unsigned s_prefix;
    __shared__ int s_need, s_out;

    const int e = blockIdx.x;
    const int tid = threadIdx.x, lane = tid & 31, wrp = tid >> 5;
    const unsigned* keys = g_keys + (size_t)e * BS_TOK;

#pragma unroll
    for (int i = 0; i < BS_TOK / (TPK_T * 4); i++) {
        uint4 v = ((const uint4*)keys)[tid + i * TPK_T];
        ((uint4*)skeys)[tid + i * TPK_T] = v;
    }
    if (tid == 0) { s_prefix = 0u; s_need = KCAP; s_out = 0; }
    __syncthreads();

    // 4 passes, 8 bits each (MSB first); uint4 strided loads
#pragma unroll
    for (int p = 3; p >= 0; p--) {
        {   // zero my warp hist (vectorized)
            uint4 z = make_uint4(0, 0, 0, 0);
#pragma unroll
            for (int i = 0; i < 2; i++)
                ((uint4*)whist)[tid + i * TPK_T] = z;
        }
        __syncthreads();
        const int sh = p * 8;
        const unsigned maskHi = (p == 3) ? 0u : (0xFFFFFFFFu << ((p + 1) * 8));
        const unsigned pref = s_prefix;
        const int need = s_need;
        unsigned* myh = whist + wrp * 256;
#pragma unroll
        for (int i = 0; i < TPK_PER / 4; i++) {
            uint4 kv = ((const uint4*)skeys)[tid + i * TPK_T];
            unsigned ks[4] = {kv.x, kv.y, kv.z, kv.w};
#pragma unroll
            for (int c = 0; c < 4; c++) {
                unsigned k = ks[c];
                bool m = ((k & maskHi) == pref);
                unsigned bin = m ? ((k >> sh) & 255u) : 0xFFFFFFFFu;
                unsigned peers = __match_any_sync(0xffffffffu, bin);
                if (m && lane == (__ffs(peers) - 1))
                    myh[bin] += (unsigned)__popc(peers);
            }
        }
        __syncthreads();
        if (tid < 256) {
            unsigned sv = 0;
#pragma unroll
            for (int w2 = 0; w2 < 32; w2++) sv += whist[w2 * 256 + tid];
            suf[tid] = sv;
        }
        __syncthreads();
        // single-warp suffix scan: lane owns 8 bins in registers
        if (wrp == 0) {
            unsigned v[8];
            unsigned tot = 0;
#pragma unroll
            for (int j = 0; j < 8; j++) { v[j] = suf[lane * 8 + j]; tot += v[j]; }
            unsigned sv = tot;
#pragma unroll
            for (int o = 1; o < 32; o <<= 1) {
                unsigned t = __shfl_down_sync(0xffffffffu, sv, o);
                if (lane + o < 32) sv += t;
            }
            unsigned acc = sv - tot;         // sum over lanes > lane
#pragma unroll
            for (int j = 7; j >= 0; j--) { acc += v[j]; v[j] = acc; }
#pragma unroll
            for (int j = 0; j < 8; j++) suf[lane * 8 + j] = v[j];
        }
        __syncthreads();
        if (tid < 256) {
            unsigned nxt = (tid == 255) ? 0u : suf[tid + 1];
            if ((int)suf[tid] >= need && (int)nxt < need) {
                s_prefix = pref | ((unsigned)tid << sh);
                s_need = need - (int)nxt;
            }
        }
        __syncthreads();
    }

    const unsigned T = s_prefix;
    const int needEq = s_need;

    // blocked partition + shuffle-hierarchical rank scan; uint4 loads
    const int base = tid * TPK_PER;
    unsigned kl[TPK_PER];
#pragma unroll
    for (int j4 = 0; j4 < TPK_PER / 4; j4++) {
        uint4 kv = ((const uint4*)(skeys + base))[j4];
        kl[j4*4]   = kv.x; kl[j4*4+1] = kv.y;
        kl[j4*4+2] = kv.z; kl[j4*4+3] = kv.w;
    }
    int cnt = 0;
#pragma unroll
    for (int j = 0; j < TPK_PER; j++) cnt += (kl[j] == T);
    int inc = cnt;
#pragma unroll
    for (int o = 1; o < 32; o <<= 1) {
        int t = __shfl_up_sync(0xffffffffu, inc, o);
        if (lane >= o) inc += t;
    }
    if (lane == 31) wsum[wrp] = inc;
    __syncthreads();
    if (tid < 32) {
        int v = wsum[tid];
        int sc = v;
#pragma unroll
        for (int o = 1; o < 32; o <<= 1) {
            int t = __shfl_up_sync(0xffffffffu, sc, o);
            if (lane >= o) sc += t;
        }
        wsum[tid] = sc - v;                  // exclusive warp base
    }
    __syncthreads();
    int r = wsum[wrp] + inc - cnt;           // exclusive rank base
#pragma unroll
    for (int j = 0; j < TPK_PER; j++) {
        int t = base + j;
        unsigned k = kl[j];
        bool sel;
        if (k > T) sel = true;
        else if (k == T) { sel = (r < needEq); r++; }
        else sel = false;
        if (sel) {
            int slot = atomicAdd(&s_out, 1);
            g_selidx[e * KCAP + slot] = t;
            g_selw  [e * KCAP + slot] = g_scores[(size_t)e * BS_TOK + t];
            g_t2s[t * NEXP + e] = e * KCAP + slot;
        }
    }
}

// ---------------- mma.sync GEMM: 128x256x64 tiles, 4-stage cp.async --------
#define BM 128
#define BN 256
#define BK 64
#define NSTG 4
#define STGB ((BM + BN) * BK * 2)     // 49152 bytes per stage
#define GEMM_SMEM (NSTG * STGB)       // 196608

__device__ __forceinline__ float gelu_f(float v) {
    float u = 0.7978845608028654f * (v + 0.044715f * v * v * v);
    float e = __expf(2.f * u);
    float th = 1.f - __fdividef(2.f, e + 1.f);
    return 0.5f * v * (1.f + th);
}

// EPI==1: g_H = gelu(LN(x)[tok] @ W1^T + b1) bf16.  EPI==2: g_O[slot]=(acc+b2)*w
template <int EPI, int M, int N, int K>
__global__ __launch_bounds__(256, 1) void mma_gemm(const float* __restrict__ bias) {
    extern __shared__ __align__(1024) char smdyn[];
    const int tid = threadIdx.x, wid = tid >> 5, lane = tid & 31;
    const int wm = wid >> 2, wn = wid & 3;           // 2 x 4 warps, 64x64 tiles
    const int e = blockIdx.z;
    uint32_t sb = smem_u32(smdyn);

    const int GX = N / BN;
    int lin = blockIdx.y * GX + blockIdx.x;
    int bm, bn;
    {
        int inb = lin % (8 * GX);
        int g2 = lin / (8 * GX);
        bm = g2 * 8 + (inb & 7);
        bn = inb >> 3;
    }

    const __nv_bfloat16* B = ((EPI == 1) ? g_w1 : g_w2) +
                             ((size_t)e * N + (size_t)bn * BN) * (size_t)K;
    const __nv_bfloat16* A2 = g_H + ((size_t)e * M + (size_t)bm * BM) * (size_t)K;

    __shared__ float bsm[BN];
    __shared__ int stok[BM];          // slot -> token map (EPI==1 gather)
    bsm[tid] = bias[(size_t)e * N + bn * BN + tid];
    if (EPI == 1 && tid < BM) stok[tid] = g_selidx[e * KCAP + bm * BM + tid];
    __syncthreads();

    auto fill = [&](int c, int s) {
        uint32_t abase = sb + s * STGB;
        uint32_t bbase = abase + BM * BK * 2;     // +16KB
        const __nv_bfloat16* gb = B + c * BK;
#pragma unroll
        for (int t = 0; t < 4; t++) {
            int i = tid + t * 256;
            int row = i >> 3, seg = i & 7;
            uint32_t off = (uint32_t)(row * 128 + seg * 16);
            off ^= (off >> 3) & 0x70u;
            const __nv_bfloat16* ga;
            if (EPI == 1)
                ga = g_xln + (size_t)stok[row] * K + c * BK + seg * 8;
            else
                ga = A2 + (size_t)row * K + c * BK + seg * 8;
            asm volatile("cp.async.cg.shared.global [%0], [%1], 16;"
                         :: "r"(abase + off), "l"(ga));
        }
#pragma unroll
        for (int t = 0; t < 8; t++) {
            int i = tid + t * 256;
            int row = i >> 3, seg = i & 7;
            uint32_t off = (uint32_t)(row * 128 + seg * 16);
            off ^= (off >> 3) & 0x70u;
            asm volatile("cp.async.cg.shared.global [%0], [%1], 16;"
                         :: "r"(bbase + off), "l"(gb + (size_t)row * K + seg * 8));
        }
        asm volatile("cp.async.commit_group;" ::: "memory");
    };

    float c[4][8][4];
#pragma unroll
    for (int a = 0; a < 4; a++)
#pragma unroll
        for (int b = 0; b < 8; b++)
#pragma unroll
            for (int d = 0; d < 4; d++) c[a][b][d] = 0.f;

    const int nk = K / BK;
    fill(0, 0); fill(1, 1); fill(2, 2);

    for (int kc = 0; kc < nk; kc++) {
        int rem = nk - 1 - kc;
        if (rem >= 2) cp_wait<2>();
        else if (rem == 1) cp_wait<1>();
        else cp_wait<0>();
        __syncthreads();
        if (kc + 3 < nk) fill(kc + 3, (kc + 3) & 3);

        uint32_t abase = sb + (kc & 3) * STGB;
        uint32_t bbase = abase + BM * BK * 2;

#pragma unroll
        for (int ks = 0; ks < 4; ks++) {
            uint32_t a[4][4], b[8][2];
            int ar = wm * 64 + (lane & 15);
            int ac = ks * 32 + (lane >> 4) * 16;
#pragma unroll
            for (int mi = 0; mi < 4; mi++) {
                uint32_t off = (uint32_t)((ar + mi * 16) * 128 + ac);
                off ^= (off >> 3) & 0x70u;
                asm volatile(
                    "ldmatrix.sync.aligned.m8n8.x4.shared.b16 {%0,%1,%2,%3}, [%4];"
                    : "=r"(a[mi][0]), "=r"(a[mi][1]), "=r"(a[mi][2]), "=r"(a[mi][3])
                    : "r"(abase + off));
            }
            int nr = wn * 64 + (lane & 7) + ((lane >> 4) << 3);
            int kb = ks * 32 + ((lane >> 3) & 1) * 16;
#pragma unroll
            for (int nb = 0; nb < 4; nb++) {
                uint32_t off = (uint32_t)((nr + nb * 16) * 128 + kb);
                off ^= (off >> 3) & 0x70u;
                asm volatile(
                    "ldmatrix.sync.aligned.m8n8.x4.shared.b16 {%0,%1,%2,%3}, [%4];"
                    : "=r"(b[2*nb][0]), "=r"(b[2*nb][1]),
                      "=r"(b[2*nb+1][0]), "=r"(b[2*nb+1][1])
                    : "r"(bbase + off));
            }
#pragma unroll
            for (int mi = 0; mi < 4; mi++)
#pragma unroll
                for (int ni = 0; ni < 8; ni++) {
                    asm volatile(
                        "mma.sync.aligned.m16n8k16.row.col.f32.bf16.bf16.f32 "
                        "{%0,%1,%2,%3}, {%4,%5,%6,%7}, {%8,%9}, {%0,%1,%2,%3};"
                        : "+f"(c[mi][ni][0]), "+f"(c[mi][ni][1]),
                          "+f"(c[mi][ni][2]), "+f"(c[mi][ni][3])
                        : "r"(a[mi][0]), "r"(a[mi][1]), "r"(a[mi][2]), "r"(a[mi][3]),
                          "r"(b[ni][0]), "r"(b[ni][1]));
                }
        }
        __syncthreads();
    }

    // -------- epilogue --------
    int g4 = lane >> 2, tg2 = (lane & 3) * 2;
    if (EPI == 1) {
#pragma unroll
        for (int mi = 0; mi < 4; mi++) {
            int row = bm * BM + wm * 64 + mi * 16 + g4;
            size_t h0 = ((size_t)e * M + row) * (size_t)N;
            size_t h1 = ((size_t)e * M + row + 8) * (size_t)N;
#pragma unroll
            for (int ni = 0; ni < 8; ni++) {
                int lc = wn * 64 + ni * 8 + tg2;
                int col = bn * BN + lc;
                float bb0 = bsm[lc], bb1 = bsm[lc + 1];
                *(__nv_bfloat162*)(g_H + h0 + col) = __floats2bfloat162_rn(
                    gelu_f(c[mi][ni][0] + bb0), gelu_f(c[mi][ni][1] + bb1));
                *(__nv_bfloat162*)(g_H + h1 + col) = __floats2bfloat162_rn(
                    gelu_f(c[mi][ni][2] + bb0), gelu_f(c[mi][ni][3] + bb1));
            }
        }
    } else {
#pragma unroll
        for (int mi = 0; mi < 4; mi++) {
            int row = bm * BM + wm * 64 + mi * 16 + g4;
            float w0 = g_selw[e * KCAP + row];
            float w1 = g_selw[e * KCAP + row + 8];
            size_t o0 = ((size_t)e * M + row) * (size_t)N;
            size_t o1 = ((size_t)e * M + row + 8) * (size_t)N;
#pragma unroll
            for (int ni = 0; ni < 8; ni++) {
                int lc = wn * 64 + ni * 8 + tg2;
                int col = bn * BN + lc;
                float bb0 = bsm[lc], bb1 = bsm[lc + 1];
                float2 v0 = make_float2((c[mi][ni][0] + bb0) * w0,
                                        (c[mi][ni][1] + bb1) * w0);
                float2 v1 = make_float2((c[mi][ni][2] + bb0) * w1,
                                        (c[mi][ni][3] + bb1) * w1);
                *(float2*)(g_O + o0 + col) = v0;
                *(float2*)(g_O + o1 + col) = v1;
            }
        }
    }
}

// ---------------- final combine (4 tokens/block) ---------------------------
__global__ void combine_kernel(const float* __restrict__ x,
                               float* __restrict__ out) {
    int t0 = blockIdx.x * 4;
    int j = threadIdx.x;
    __shared__ int sl[4][NEXP];
    if (j < 4 * NEXP) sl[j >> 3][j & 7] = g_t2s[t0 * NEXP + j];
    float4 a[4];
#pragma unroll
    for (int tk = 0; tk < 4; tk++)
        a[tk] = ((const float4*)(x + (size_t)(t0 + tk) * DIM))[j];
    __syncthreads();
#pragma unroll
    for (int e = 0; e < NEXP; e++) {
#pragma unroll
        for (int tk = 0; tk < 4; tk++) {
            int s = sl[tk][e];
            if (s >= 0) {
                float4 o = ((const float4*)(g_O + (size_t)s * DIM))[j];
                a[tk].x += o.x; a[tk].y += o.y; a[tk].z += o.z; a[tk].w += o.w;
            }
        }
    }
#pragma unroll
    for (int tk = 0; tk < 4; tk++)
        ((float4*)(out + (size_t)(t0 + tk) * DIM))[j] = a[tk];
}

// ---------------- launch ---------------------------------------------------
extern "C" void kernel_launch(void* const* d_in, const int* in_sizes, int n_in,
                              void* d_out, int out_size) {
    const float* x   = (const float*)d_in[0];
    const float* gw  = (const float*)d_in[1];
    const float* lnw = (const float*)d_in[2];
    const float* lnb = (const float*)d_in[3];
    const float* fc1 = (const float*)d_in[4];
    const float* b1  = (const float*)d_in[5];
    const float* fc2 = (const float*)d_in[6];
    const float* b2  = (const float*)d_in[7];
    float* out = (float*)d_out;

    cudaFuncSetAttribute(mma_gemm<1, KCAP, DDIM, DIM>,
                         cudaFuncAttributeMaxDynamicSharedMemorySize, GEMM_SMEM);
    cudaFuncSetAttribute(mma_gemm<2, KCAP, DIM, DDIM>,
                         cudaFuncAttributeMaxDynamicSharedMemorySize, GEMM_SMEM);
    cudaFuncSetAttribute(topk_kernel,
                         cudaFuncAttributeMaxDynamicSharedMemorySize, TPK_SMEM);

    // fork: side stream converts w1 (joins GEMM1) then w2 (joins GEMM2,
    // hidden under GEMM1). Main stream: gate_ln -> topk.
    cudaStream_t sB;
    cudaStreamCreateWithFlags(&sB, cudaStreamNonBlocking);
    cudaEvent_t evFork, evW1, evW2;
    cudaEventCreateWithFlags(&evFork, cudaEventDisableTiming);
    cudaEventCreateWithFlags(&evW1,   cudaEventDisableTiming);
    cudaEventCreateWithFlags(&evW2,   cudaEventDisableTiming);

    cudaEventRecord(evFork, 0);
    cudaStreamWaitEvent(sB, evFork, 0);
    convert_w_kernel<<<4096, 256, 0, sB>>>((const float4*)fc1, 1);
    cudaEventRecord(evW1, sB);
    convert_w_kernel<<<4096, 256, 0, sB>>>((const float4*)fc2, 2);
    cudaEventRecord(evW2, sB);

    gate_ln_kernel<<<BS_TOK / 4, 256>>>(x, gw, lnw, lnb);  // scores + x_ln + t2s init
    topk_kernel<<<NEXP, TPK_T, TPK_SMEM>>>();

    cudaStreamWaitEvent(0, evW1, 0);                  // w1 ready
    {   // GEMM1: per expert (2048 x 4096 x 1024), A gathered from x_ln
        dim3 grid(DDIM / BN, KCAP / BM, NEXP);   // (16, 16, 8)
        mma_gemm<1, KCAP, DDIM, DIM><<<grid, 256, GEMM_SMEM>>>(b1);
    }
    cudaStreamWaitEvent(0, evW2, 0);                  // w2 ready
    {   // GEMM2: per expert (2048 x 1024 x 4096), bias + gate scale -> g_O
        dim3 grid(DIM / BN, KCAP / BM, NEXP);    // (4, 16, 8)
        mma_gemm<2, KCAP, DIM, DDIM><<<grid, 256, GEMM_SMEM>>>(b2);
    }
    combine_kernel<<<BS_TOK / 4, 256>>>(x, out);
}

// round 15
// speedup vs baseline: 1.0987x; 1.0019x over previous
#include <cuda_runtime.h>
#include <cuda_bf16.h>
#include <math.h>
#include <stdint.h>

#define BS_TOK 16384
#define DIM    1024
#define DDIM   4096
#define NEXP   8
#define KCAP   2048   // tokens per expert

// ---------------- scratch (device globals; allocation-free rule) ----------
__device__ __align__(16) __nv_bfloat16 g_w1 [(size_t)NEXP * DDIM * DIM]; // 64MB
__device__ __align__(16) __nv_bfloat16 g_w2 [(size_t)NEXP * DIM * DDIM]; // 64MB
__device__ __align__(16) __nv_bfloat16 g_xln[(size_t)BS_TOK * DIM];      // 32MB (token-ordered LN(x))
__device__ __align__(16) __nv_bfloat16 g_H  [(size_t)BS_TOK * DDIM];    // 128MB
__device__ __align__(16) float g_O[(size_t)BS_TOK * DIM];                // 64MB
__device__ float    g_scores[NEXP * BS_TOK];
__device__ unsigned g_keys  [NEXP * BS_TOK];
__device__ int      g_selidx[BS_TOK];
__device__ float    g_selw  [BS_TOK];
__device__ int      g_t2s   [BS_TOK * NEXP];   // token -> slot (or -1)

// ---------------- small helpers -------------------------------------------
__device__ __forceinline__ uint32_t smem_u32(const void* p) {
    uint32_t a;
    asm("{ .reg .u64 t; cvta.to.shared.u64 t, %1; cvt.u32.u64 %0, t; }"
        : "=r"(a) : "l"(p));
    return a;
}
template <int N>
__device__ __forceinline__ void cp_wait() {
    asm volatile("cp.async.wait_group %0;" :: "n"(N) : "memory");
}

// ---------------- weight conversion fp32 -> bf16 (one matrix) -------------
__global__ void convert_w_kernel(const float4* __restrict__ src, int which) {
    size_t n = (size_t)NEXP * DDIM * DIM / 4;
    __nv_bfloat162* dst = (which == 1) ? (__nv_bfloat162*)g_w1
                                       : (__nv_bfloat162*)g_w2;
    for (size_t i = (size_t)blockIdx.x * blockDim.x + threadIdx.x; i < n;
         i += (size_t)gridDim.x * blockDim.x) {
        float4 a = src[i];
        dst[2*i]   = __floats2bfloat162_rn(a.x, a.y);
        dst[2*i+1] = __floats2bfloat162_rn(a.z, a.w);
    }
}

// -------- gating + LayerNorm fused: softmax scores + x_ln, 4 tok/block -----
__global__ void gate_ln_kernel(const float* __restrict__ x,
                               const float* __restrict__ gw,
                               const float* __restrict__ lnw,
                               const float* __restrict__ lnb) {
    int t0 = blockIdx.x * 4;
    int tid = threadIdx.x;
    if (tid < 4 * NEXP) g_t2s[t0 * NEXP + tid] = -1;   // fold t2s init
    float4 xv[4];
#pragma unroll
    for (int tk = 0; tk < 4; tk++)
        xv[tk] = ((const float4*)(x + (size_t)(t0 + tk) * DIM))[tid];
    float a[4][NEXP];
#pragma unroll
    for (int e = 0; e < NEXP; e++) {
        float4 wv = ((const float4*)(gw + (size_t)e * DIM))[tid];
#pragma unroll
        for (int tk = 0; tk < 4; tk++)
            a[tk][e] = xv[tk].x*wv.x + xv[tk].y*wv.y +
                       xv[tk].z*wv.z + xv[tk].w*wv.w;
    }
    float s[4], q[4];
#pragma unroll
    for (int tk = 0; tk < 4; tk++) {
        s[tk] = xv[tk].x + xv[tk].y + xv[tk].z + xv[tk].w;
        q[tk] = xv[tk].x*xv[tk].x + xv[tk].y*xv[tk].y +
                xv[tk].z*xv[tk].z + xv[tk].w*xv[tk].w;
    }
#pragma unroll
    for (int o = 16; o > 0; o >>= 1) {
#pragma unroll
        for (int tk = 0; tk < 4; tk++) {
#pragma unroll
            for (int e = 0; e < NEXP; e++)
                a[tk][e] += __shfl_xor_sync(0xffffffffu, a[tk][e], o);
            s[tk] += __shfl_xor_sync(0xffffffffu, s[tk], o);
            q[tk] += __shfl_xor_sync(0xffffffffu, q[tk], o);
        }
    }

    __shared__ float sh[4][8][NEXP];
    __shared__ float red[8][8];
    __shared__ float lg[4][NEXP];
    __shared__ float fin[8];
    int w = tid >> 5, l = tid & 31;
    if (l == 0) {
#pragma unroll
        for (int tk = 0; tk < 4; tk++) {
#pragma unroll
            for (int e = 0; e < NEXP; e++) sh[tk][w][e] = a[tk][e];
            red[2*tk][w] = s[tk]; red[2*tk+1][w] = q[tk];
        }
    }
    __syncthreads();
    if (tid < 32) {
        int tk = tid >> 3, e = tid & 7;
        float sv = 0.f;
#pragma unroll
        for (int i = 0; i < 8; i++) sv += sh[tk][i][e];
        lg[tk][e] = sv;
    }
    if (tid >= 32 && tid < 36) {
        int tk = tid - 32;
        float S = 0.f, Q = 0.f;
#pragma unroll
        for (int i = 0; i < 8; i++) { S += red[2*tk][i]; Q += red[2*tk+1][i]; }
        float mu = S * (1.f / DIM);
        float var = Q * (1.f / DIM) - mu * mu;
        fin[2*tk]   = mu;
        fin[2*tk+1] = rsqrtf(var + 1e-5f);
    }
    __syncthreads();
    if (tid < 32) {
        int tk = tid >> 3, e = tid & 7;
        int t = t0 + tk;
        float mx = lg[tk][0];
#pragma unroll
        for (int i = 1; i < NEXP; i++) mx = fmaxf(mx, lg[tk][i]);
        float den = 0.f;
#pragma unroll
        for (int i = 0; i < NEXP; i++) den += expf(lg[tk][i] - mx);
        float sc = expf(lg[tk][e] - mx) / den;
        g_scores[e * BS_TOK + t] = sc;
        unsigned b = __float_as_uint(sc);
        b ^= (b >> 31) ? 0xFFFFFFFFu : 0x80000000u;
        g_keys[e * BS_TOK + t] = b;
    }
    float4 wv = ((const float4*)lnw)[tid];
    float4 bv = ((const float4*)lnb)[tid];
#pragma unroll
    for (int tk = 0; tk < 4; tk++) {
        float mu = fin[2*tk], rs = fin[2*tk+1];
        __nv_bfloat162* y = (__nv_bfloat162*)(g_xln + (size_t)(t0 + tk) * DIM);
        y[tid*2]   = __floats2bfloat162_rn((xv[tk].x-mu)*rs*wv.x + bv.x,
                                           (xv[tk].y-mu)*rs*wv.y + bv.y);
        y[tid*2+1] = __floats2bfloat162_rn((xv[tk].z-mu)*rs*wv.z + bv.z,
                                           (xv[tk].w-mu)*rs*wv.w + bv.w);
    }
}

// ------- per-expert exact top-k: warp hists + ballot-guarded match ---------
#define TPK_T 1024
#define TPK_PER (BS_TOK / TPK_T)            // 16 keys per thread
#define TPK_SMEM (BS_TOK * 4 + 32 * 256 * 4) // 64KB keys + 32KB warp hists

__global__ __launch_bounds__(TPK_T, 1) void topk_kernel() {
    extern __shared__ unsigned sm[];
    unsigned* skeys = sm;                    // [BS_TOK]
    unsigned* whist = sm + BS_TOK;           // [32][256]
    __shared__ unsigned suf[256];
    __shared__ int wsum[32];
    __shared__ unsigned s_prefix;
    __shared__ int s_need, s_out;

    const int e = blockIdx.x;
    const int tid = threadIdx.x, lane = tid & 31, wrp = tid >> 5;
    const unsigned* keys = g_keys + (size_t)e * BS_TOK;

#pragma unroll
    for (int i = 0; i < BS_TOK / (TPK_T * 4); i++) {
        uint4 v = ((const uint4*)keys)[tid + i * TPK_T];
        ((uint4*)skeys)[tid + i * TPK_T] = v;
    }
    if (tid == 0) { s_prefix = 0u; s_need = KCAP; s_out = 0; }
    __syncthreads();

    // 4 passes, 8 bits each (MSB first); match guarded by warp ballot
#pragma unroll
    for (int p = 3; p >= 0; p--) {
        {   // zero my warp hist (vectorized)
            uint4 z = make_uint4(0, 0, 0, 0);
#pragma unroll
            for (int i = 0; i < 2; i++)
                ((uint4*)whist)[tid + i * TPK_T] = z;
        }
        __syncthreads();
        const int sh = p * 8;
        const unsigned maskHi = (p == 3) ? 0u : (0xFFFFFFFFu << ((p + 1) * 8));
        const unsigned pref = s_prefix;
        const int need = s_need;
        unsigned* myh = whist + wrp * 256;
#pragma unroll
        for (int i = 0; i < TPK_PER / 4; i++) {
            uint4 kv = ((const uint4*)skeys)[tid + i * TPK_T];
            unsigned ks[4] = {kv.x, kv.y, kv.z, kv.w};
#pragma unroll
            for (int c = 0; c < 4; c++) {
                unsigned k = ks[c];
                bool m = ((k & maskHi) == pref);
                // cheap warp-uniform skip: in later passes most iterations
                // have zero matching keys in the warp
                unsigned mm = __ballot_sync(0xffffffffu, m);
                if (mm != 0u) {
                    unsigned bin = m ? ((k >> sh) & 255u) : 0xFFFFFFFFu;
                    unsigned peers = __match_any_sync(0xffffffffu, bin);
                    if (m && lane == (__ffs(peers) - 1))
                        myh[bin] += (unsigned)__popc(peers);
                }
            }
        }
        __syncthreads();
        if (tid < 256) {
            unsigned sv = 0;
#pragma unroll
            for (int w2 = 0; w2 < 32; w2++) sv += whist[w2 * 256 + tid];
            suf[tid] = sv;
        }
        __syncthreads();
        // single-warp suffix scan: lane owns 8 bins in registers
        if (wrp == 0) {
            unsigned v[8];
            unsigned tot = 0;
#pragma unroll
            for (int j = 0; j < 8; j++) { v[j] = suf[lane * 8 + j]; tot += v[j]; }
            unsigned sv = tot;
#pragma unroll
            for (int o = 1; o < 32; o <<= 1) {
                unsigned t = __shfl_down_sync(0xffffffffu, sv, o);
                if (lane + o < 32) sv += t;
            }
            unsigned acc = sv - tot;         // sum over lanes > lane
#pragma unroll
            for (int j = 7; j >= 0; j--) { acc += v[j]; v[j] = acc; }
#pragma unroll
            for (int j = 0; j < 8; j++) suf[lane * 8 + j] = v[j];
        }
        __syncthreads();
        if (tid < 256) {
            unsigned nxt = (tid == 255) ? 0u : suf[tid + 1];
            if ((int)suf[tid] >= need && (int)nxt < need) {
                s_prefix = pref | ((unsigned)tid << sh);
                s_need = need - (int)nxt;
            }
        }
        __syncthreads();
    }

    const unsigned T = s_prefix;
    const int needEq = s_need;

    // blocked partition + shuffle-hierarchical rank scan; uint4 loads
    const int base = tid * TPK_PER;
    unsigned kl[TPK_PER];
#pragma unroll
    for (int j4 = 0; j4 < TPK_PER / 4; j4++) {
        uint4 kv = ((const uint4*)(skeys + base))[j4];
        kl[j4*4]   = kv.x; kl[j4*4+1] = kv.y;
        kl[j4*4+2] = kv.z; kl[j4*4+3] = kv.w;
    }
    int cnt = 0;
#pragma unroll
    for (int j = 0; j < TPK_PER; j++) cnt += (kl[j] == T);
    int inc = cnt;
#pragma unroll
    for (int o = 1; o < 32; o <<= 1) {
        int t = __shfl_up_sync(0xffffffffu, inc, o);
        if (lane >= o) inc += t;
    }
    if (lane == 31) wsum[wrp] = inc;
    __syncthreads();
    if (tid < 32) {
        int v = wsum[tid];
        int sc = v;
#pragma unroll
        for (int o = 1; o < 32; o <<= 1) {
            int t = __shfl_up_sync(0xffffffffu, sc, o);
            if (lane >= o) sc += t;
        }
        wsum[tid] = sc - v;                  // exclusive warp base
    }
    __syncthreads();
    int r = wsum[wrp] + inc - cnt;           // exclusive rank base
#pragma unroll
    for (int j = 0; j < TPK_PER; j++) {
        int t = base + j;
        unsigned k = kl[j];
        bool sel;
        if (k > T) sel = true;
        else if (k == T) { sel = (r < needEq); r++; }
        else sel = false;
        if (sel) {
            int slot = atomicAdd(&s_out, 1);
            g_selidx[e * KCAP + slot] = t;
            g_selw  [e * KCAP + slot] = g_scores[(size_t)e * BS_TOK + t];
            g_t2s[t * NEXP + e] = e * KCAP + slot;
        }
    }
}

// ---------------- mma.sync GEMM: 128x256x64 tiles, 4-stage cp.async --------
#define BM 128
#define BN 256
#define BK 64
#define NSTG 4
#define STGB ((BM + BN) * BK * 2)     // 49152 bytes per stage
#define GEMM_SMEM (NSTG * STGB)       // 196608

__device__ __forceinline__ float gelu_f(float v) {
    float u = 0.7978845608028654f * (v + 0.044715f * v * v * v);
    float e = __expf(2.f * u);
    float th = 1.f - __fdividef(2.f, e + 1.f);
    return 0.5f * v * (1.f + th);
}

// EPI==1: g_H = gelu(LN(x)[tok] @ W1^T + b1) bf16.  EPI==2: g_O[slot]=(acc+b2)*w
template <int EPI, int M, int N, int K>
__global__ __launch_bounds__(256, 1) void mma_gemm(const float* __restrict__ bias) {
    extern __shared__ __align__(1024) char smdyn[];
    const int tid = threadIdx.x, wid = tid >> 5, lane = tid & 31;
    const int wm = wid >> 2, wn = wid & 3;           // 2 x 4 warps, 64x64 tiles
    const int e = blockIdx.z;
    uint32_t sb = smem_u32(smdyn);

    const int GX = N / BN;
    int lin = blockIdx.y * GX + blockIdx.x;
    int bm, bn;
    {
        int inb = lin % (8 * GX);
        int g2 = lin / (8 * GX);
        bm = g2 * 8 + (inb & 7);
        bn = inb >> 3;
    }

    const __nv_bfloat16* B = ((EPI == 1) ? g_w1 : g_w2) +
                             ((size_t)e * N + (size_t)bn * BN) * (size_t)K;
    const __nv_bfloat16* A2 = g_H + ((size_t)e * M + (size_t)bm * BM) * (size_t)K;

    __shared__ float bsm[BN];
    __shared__ int stok[BM];          // slot -> token map (EPI==1 gather)
    bsm[tid] = bias[(size_t)e * N + bn * BN + tid];
    if (EPI == 1 && tid < BM) stok[tid] = g_selidx[e * KCAP + bm * BM + tid];
    __syncthreads();

    auto fill = [&](int c, int s) {
        uint32_t abase = sb + s * STGB;
        uint32_t bbase = abase + BM * BK * 2;     // +16KB
        const __nv_bfloat16* gb = B + c * BK;
#pragma unroll
        for (int t = 0; t < 4; t++) {
            int i = tid + t * 256;
            int row = i >> 3, seg = i & 7;
            uint32_t off = (uint32_t)(row * 128 + seg * 16);
            off ^= (off >> 3) & 0x70u;
            const __nv_bfloat16* ga;
            if (EPI == 1)
                ga = g_xln + (size_t)stok[row] * K + c * BK + seg * 8;
            else
                ga = A2 + (size_t)row * K + c * BK + seg * 8;
            asm volatile("cp.async.cg.shared.global [%0], [%1], 16;"
                         :: "r"(abase + off), "l"(ga));
        }
#pragma unroll
        for (int t = 0; t < 8; t++) {
            int i = tid + t * 256;
            int row = i >> 3, seg = i & 7;
            uint32_t off = (uint32_t)(row * 128 + seg * 16);
            off ^= (off >> 3) & 0x70u;
            asm volatile("cp.async.cg.shared.global [%0], [%1], 16;"
                         :: "r"(bbase + off), "l"(gb + (size_t)row * K + seg * 8));
        }
        asm volatile("cp.async.commit_group;" ::: "memory");
    };

    float c[4][8][4];
#pragma unroll
    for (int a = 0; a < 4; a++)
#pragma unroll
        for (int b = 0; b < 8; b++)
#pragma unroll
            for (int d = 0; d < 4; d++) c[a][b][d] = 0.f;

    const int nk = K / BK;
    fill(0, 0); fill(1, 1); fill(2, 2);

    for (int kc = 0; kc < nk; kc++) {
        int rem = nk - 1 - kc;
        if (rem >= 2) cp_wait<2>();
        else if (rem == 1) cp_wait<1>();
        else cp_wait<0>();
        __syncthreads();
        if (kc + 3 < nk) fill(kc + 3, (kc + 3) & 3);

        uint32_t abase = sb + (kc & 3) * STGB;
        uint32_t bbase = abase + BM * BK * 2;

#pragma unroll
        for (int ks = 0; ks < 4; ks++) {
            uint32_t a[4][4], b[8][2];
            int ar = wm * 64 + (lane & 15);
            int ac = ks * 32 + (lane >> 4) * 16;
#pragma unroll
            for (int mi = 0; mi < 4; mi++) {
                uint32_t off = (uint32_t)((ar + mi * 16) * 128 + ac);
                off ^= (off >> 3) & 0x70u;
                asm volatile(
                    "ldmatrix.sync.aligned.m8n8.x4.shared.b16 {%0,%1,%2,%3}, [%4];"
                    : "=r"(a[mi][0]), "=r"(a[mi][1]), "=r"(a[mi][2]), "=r"(a[mi][3])
                    : "r"(abase + off));
            }
            int nr = wn * 64 + (lane & 7) + ((lane >> 4) << 3);
            int kb = ks * 32 + ((lane >> 3) & 1) * 16;
#pragma unroll
            for (int nb = 0; nb < 4; nb++) {
                uint32_t off = (uint32_t)((nr + nb * 16) * 128 + kb);
                off ^= (off >> 3) & 0x70u;
                asm volatile(
                    "ldmatrix.sync.aligned.m8n8.x4.shared.b16 {%0,%1,%2,%3}, [%4];"
                    : "=r"(b[2*nb][0]), "=r"(b[2*nb][1]),
                      "=r"(b[2*nb+1][0]), "=r"(b[2*nb+1][1])
                    : "r"(bbase + off));
            }
#pragma unroll
            for (int mi = 0; mi < 4; mi++)
#pragma unroll
                for (int ni = 0; ni < 8; ni++) {
                    asm volatile(
                        "mma.sync.aligned.m16n8k16.row.col.f32.bf16.bf16.f32 "
                        "{%0,%1,%2,%3}, {%4,%5,%6,%7}, {%8,%9}, {%0,%1,%2,%3};"
                        : "+f"(c[mi][ni][0]), "+f"(c[mi][ni][1]),
                          "+f"(c[mi][ni][2]), "+f"(c[mi][ni][3])
                        : "r"(a[mi][0]), "r"(a[mi][1]), "r"(a[mi][2]), "r"(a[mi][3]),
                          "r"(b[ni][0]), "r"(b[ni][1]));
                }
        }
        __syncthreads();
    }

    // -------- epilogue --------
    int g4 = lane >> 2, tg2 = (lane & 3) * 2;
    if (EPI == 1) {
#pragma unroll
        for (int mi = 0; mi < 4; mi++) {
            int row = bm * BM + wm * 64 + mi * 16 + g4;
            size_t h0 = ((size_t)e * M + row) * (size_t)N;
            size_t h1 = ((size_t)e * M + row + 8) * (size_t)N;
#pragma unroll
            for (int ni = 0; ni < 8; ni++) {
                int lc = wn * 64 + ni * 8 + tg2;
                int col = bn * BN + lc;
                float bb0 = bsm[lc], bb1 = bsm[lc + 1];
                *(__nv_bfloat162*)(g_H + h0 + col) = __floats2bfloat162_rn(
                    gelu_f(c[mi][ni][0] + bb0), gelu_f(c[mi][ni][1] + bb1));
                *(__nv_bfloat162*)(g_H + h1 + col) = __floats2bfloat162_rn(
                    gelu_f(c[mi][ni][2] + bb0), gelu_f(c[mi][ni][3] + bb1));
            }
        }
    } else {
#pragma unroll
        for (int mi = 0; mi < 4; mi++) {
            int row = bm * BM + wm * 64 + mi * 16 + g4;
            float w0 = g_selw[e * KCAP + row];
            float w1 = g_selw[e * KCAP + row + 8];
            size_t o0 = ((size_t)e * M + row) * (size_t)N;
            size_t o1 = ((size_t)e * M + row + 8) * (size_t)N;
#pragma unroll
            for (int ni = 0; ni < 8; ni++) {
                int lc = wn * 64 + ni * 8 + tg2;
                int col = bn * BN + lc;
                float bb0 = bsm[lc], bb1 = bsm[lc + 1];
                float2 v0 = make_float2((c[mi][ni][0] + bb0) * w0,
                                        (c[mi][ni][1] + bb1) * w0);
                float2 v1 = make_float2((c[mi][ni][2] + bb0) * w1,
                                        (c[mi][ni][3] + bb1) * w1);
                *(float2*)(g_O + o0 + col) = v0;
                *(float2*)(g_O + o1 + col) = v1;
            }
        }
    }
}

// ---------------- final combine (4 tokens/block) ---------------------------
__global__ void combine_kernel(const float* __restrict__ x,
                               float* __restrict__ out) {
    int t0 = blockIdx.x * 4;
    int j = threadIdx.x;
    __shared__ int sl[4][NEXP];
    if (j < 4 * NEXP) sl[j >> 3][j & 7] = g_t2s[t0 * NEXP + j];
    float4 a[4];
#pragma unroll
    for (int tk = 0; tk < 4; tk++)
        a[tk] = ((const float4*)(x + (size_t)(t0 + tk) * DIM))[j];
    __syncthreads();
#pragma unroll
    for (int e = 0; e < NEXP; e++) {
#pragma unroll
        for (int tk = 0; tk < 4; tk++) {
            int s = sl[tk][e];
            if (s >= 0) {
                float4 o = ((const float4*)(g_O + (size_t)s * DIM))[j];
                a[tk].x += o.x; a[tk].y += o.y; a[tk].z += o.z; a[tk].w += o.w;
            }
        }
    }
#pragma unroll
    for (int tk = 0; tk < 4; tk++)
        ((float4*)(out + (size_t)(t0 + tk) * DIM))[j] = a[tk];
}

// ---------------- launch ---------------------------------------------------
extern "C" void kernel_launch(void* const* d_in, const int* in_sizes, int n_in,
                              void* d_out, int out_size) {
    const float* x   = (const float*)d_in[0];
    const float* gw  = (const float*)d_in[1];
    const float* lnw = (const float*)d_in[2];
    const float* lnb = (const float*)d_in[3];
    const float* fc1 = (const float*)d_in[4];
    const float* b1  = (const float*)d_in[5];
    const float* fc2 = (const float*)d_in[6];
    const float* b2  = (const float*)d_in[7];
    float* out = (float*)d_out;

    cudaFuncSetAttribute(mma_gemm<1, KCAP, DDIM, DIM>,
                         cudaFuncAttributeMaxDynamicSharedMemorySize, GEMM_SMEM);
    cudaFuncSetAttribute(mma_gemm<2, KCAP, DIM, DDIM>,
                         cudaFuncAttributeMaxDynamicSharedMemorySize, GEMM_SMEM);
    cudaFuncSetAttribute(topk_kernel,
                         cudaFuncAttributeMaxDynamicSharedMemorySize, TPK_SMEM);

    // fork: side stream converts w1 (joins GEMM1) then w2 (joins GEMM2,
    // hidden under GEMM1). Main stream: gate_ln -> topk.
    cudaStream_t sB;
    cudaStreamCreateWithFlags(&sB, cudaStreamNonBlocking);
    cudaEvent_t evFork, evW1, evW2;
    cudaEventCreateWithFlags(&evFork, cudaEventDisableTiming);
    cudaEventCreateWithFlags(&evW1,   cudaEventDisableTiming);
    cudaEventCreateWithFlags(&evW2,   cudaEventDisableTiming);

    cudaEventRecord(evFork, 0);
    cudaStreamWaitEvent(sB, evFork, 0);
    convert_w_kernel<<<4096, 256, 0, sB>>>((const float4*)fc1, 1);
    cudaEventRecord(evW1, sB);
    convert_w_kernel<<<4096, 256, 0, sB>>>((const float4*)fc2, 2);
    cudaEventRecord(evW2, sB);

    gate_ln_kernel<<<BS_TOK / 4, 256>>>(x, gw, lnw, lnb);  // scores + x_ln + t2s init
    topk_kernel<<<NEXP, TPK_T, TPK_SMEM>>>();

    cudaStreamWaitEvent(0, evW1, 0);                  // w1 ready
    {   // GEMM1: per expert (2048 x 4096 x 1024), A gathered from x_ln
        dim3 grid(DDIM / BN, KCAP / BM, NEXP);   // (16, 16, 8)
        mma_gemm<1, KCAP, DDIM, DIM><<<grid, 256, GEMM_SMEM>>>(b1);
    }
    cudaStreamWaitEvent(0, evW2, 0);                  // w2 ready
    {   // GEMM2: per expert (2048 x 1024 x 4096), bias + gate scale -> g_O
        dim3 grid(DIM / BN, KCAP / BM, NEXP);    // (4, 16, 8)
        mma_gemm<2, KCAP, DIM, DDIM><<<grid, 256, GEMM_SMEM>>>(b2);
    }
    combine_kernel<<<BS_TOK / 4, 256>>>(x, out);
}

// round 16
// speedup vs baseline: 1.1081x; 1.0085x over previous
#include <cuda_runtime.h>
#include <cuda_bf16.h>
#include <math.h>
#include <stdint.h>

#define BS_TOK 16384
#define DIM    1024
#define DDIM   4096
#define NEXP   8
#define KCAP   2048   // tokens per expert

// ---------------- scratch (device globals; allocation-free rule) ----------
__device__ __align__(16) __nv_bfloat16 g_w1 [(size_t)NEXP * DDIM * DIM]; // 64MB
__device__ __align__(16) __nv_bfloat16 g_w2 [(size_t)NEXP * DIM * DDIM]; // 64MB
__device__ __align__(16) __nv_bfloat16 g_xln[(size_t)BS_TOK * DIM];      // 32MB (token-ordered LN(x))
__device__ __align__(16) __nv_bfloat16 g_H  [(size_t)BS_TOK * DDIM];    // 128MB
__device__ __align__(16) __nv_bfloat16 g_O  [(size_t)BS_TOK * DIM];     // 32MB (bf16 expert outputs)
__device__ float    g_scores[NEXP * BS_TOK];
__device__ unsigned g_keys  [NEXP * BS_TOK];
__device__ int      g_selidx[BS_TOK];
__device__ float    g_selw  [BS_TOK];
__device__ int      g_t2s   [BS_TOK * NEXP];   // token -> slot (or -1)

// ---------------- small helpers -------------------------------------------
__device__ __forceinline__ uint32_t smem_u32(const void* p) {
    uint32_t a;
    asm("{ .reg .u64 t; cvta.to.shared.u64 t, %1; cvt.u32.u64 %0, t; }"
        : "=r"(a) : "l"(p));
    return a;
}
template <int N>
__device__ __forceinline__ void cp_wait() {
    asm volatile("cp.async.wait_group %0;" :: "n"(N) : "memory");
}

// ---------------- weight conversion fp32 -> bf16 (one matrix) -------------
__global__ void convert_w_kernel(const float4* __restrict__ src, int which) {
    size_t n = (size_t)NEXP * DDIM * DIM / 4;
    __nv_bfloat162* dst = (which == 1) ? (__nv_bfloat162*)g_w1
                                       : (__nv_bfloat162*)g_w2;
    for (size_t i = (size_t)blockIdx.x * blockDim.x + threadIdx.x; i < n;
         i += (size_t)gridDim.x * blockDim.x) {
        float4 a = src[i];
        dst[2*i]   = __floats2bfloat162_rn(a.x, a.y);
        dst[2*i+1] = __floats2bfloat162_rn(a.z, a.w);
    }
}

// -------- gating + LayerNorm fused: softmax scores + x_ln, 4 tok/block -----
__global__ void gate_ln_kernel(const float* __restrict__ x,
                               const float* __restrict__ gw,
                               const float* __restrict__ lnw,
                               const float* __restrict__ lnb) {
    int t0 = blockIdx.x * 4;
    int tid = threadIdx.x;
    if (tid < 4 * NEXP) g_t2s[t0 * NEXP + tid] = -1;   // fold t2s init
    float4 xv[4];
#pragma unroll
    for (int tk = 0; tk < 4; tk++)
        xv[tk] = ((const float4*)(x + (size_t)(t0 + tk) * DIM))[tid];
    float a[4][NEXP];
#pragma unroll
    for (int e = 0; e < NEXP; e++) {
        float4 wv = ((const float4*)(gw + (size_t)e * DIM))[tid];
#pragma unroll
        for (int tk = 0; tk < 4; tk++)
            a[tk][e] = xv[tk].x*wv.x + xv[tk].y*wv.y +
                       xv[tk].z*wv.z + xv[tk].w*wv.w;
    }
    float s[4], q[4];
#pragma unroll
    for (int tk = 0; tk < 4; tk++) {
        s[tk] = xv[tk].x + xv[tk].y + xv[tk].z + xv[tk].w;
        q[tk] = xv[tk].x*xv[tk].x + xv[tk].y*xv[tk].y +
                xv[tk].z*xv[tk].z + xv[tk].w*xv[tk].w;
    }
#pragma unroll
    for (int o = 16; o > 0; o >>= 1) {
#pragma unroll
        for (int tk = 0; tk < 4; tk++) {
#pragma unroll
            for (int e = 0; e < NEXP; e++)
                a[tk][e] += __shfl_xor_sync(0xffffffffu, a[tk][e], o);
            s[tk] += __shfl_xor_sync(0xffffffffu, s[tk], o);
            q[tk] += __shfl_xor_sync(0xffffffffu, q[tk], o);
        }
    }

    __shared__ float sh[4][8][NEXP];
    __shared__ float red[8][8];
    __shared__ float lg[4][NEXP];
    __shared__ float fin[8];
    int w = tid >> 5, l = tid & 31;
    if (l == 0) {
#pragma unroll
        for (int tk = 0; tk < 4; tk++) {
#pragma unroll
            for (int e = 0; e < NEXP; e++) sh[tk][w][e] = a[tk][e];
            red[2*tk][w] = s[tk]; red[2*tk+1][w] = q[tk];
        }
    }
    __syncthreads();
    if (tid < 32) {
        int tk = tid >> 3, e = tid & 7;
        float sv = 0.f;
#pragma unroll
        for (int i = 0; i < 8; i++) sv += sh[tk][i][e];
        lg[tk][e] = sv;
    }
    if (tid >= 32 && tid < 36) {
        int tk = tid - 32;
        float S = 0.f, Q = 0.f;
#pragma unroll
        for (int i = 0; i < 8; i++) { S += red[2*tk][i]; Q += red[2*tk+1][i]; }
        float mu = S * (1.f / DIM);
        float var = Q * (1.f / DIM) - mu * mu;
        fin[2*tk]   = mu;
        fin[2*tk+1] = rsqrtf(var + 1e-5f);
    }
    __syncthreads();
    if (tid < 32) {
        int tk = tid >> 3, e = tid & 7;
        int t = t0 + tk;
        float mx = lg[tk][0];
#pragma unroll
        for (int i = 1; i < NEXP; i++) mx = fmaxf(mx, lg[tk][i]);
        float den = 0.f;
#pragma unroll
        for (int i = 0; i < NEXP; i++) den += expf(lg[tk][i] - mx);
        float sc = expf(lg[tk][e] - mx) / den;
        g_scores[e * BS_TOK + t] = sc;
        unsigned b = __float_as_uint(sc);
        b ^= (b >> 31) ? 0xFFFFFFFFu : 0x80000000u;
        g_keys[e * BS_TOK + t] = b;
    }
    float4 wv = ((const float4*)lnw)[tid];
    float4 bv = ((const float4*)lnb)[tid];
#pragma unroll
    for (int tk = 0; tk < 4; tk++) {
        float mu = fin[2*tk], rs = fin[2*tk+1];
        __nv_bfloat162* y = (__nv_bfloat162*)(g_xln + (size_t)(t0 + tk) * DIM);
        y[tid*2]   = __floats2bfloat162_rn((xv[tk].x-mu)*rs*wv.x + bv.x,
                                           (xv[tk].y-mu)*rs*wv.y + bv.y);
        y[tid*2+1] = __floats2bfloat162_rn((xv[tk].z-mu)*rs*wv.z + bv.z,
                                           (xv[tk].w-mu)*rs*wv.w + bv.w);
    }
}

// ------- per-expert exact top-k: warp hists + ballot-guarded match ---------
#define TPK_T 1024
#define TPK_PER (BS_TOK / TPK_T)            // 16 keys per thread
#define TPK_SMEM (BS_TOK * 4 + 32 * 256 * 4) // 64KB keys + 32KB warp hists

__global__ __launch_bounds__(TPK_T, 1) void topk_kernel() {
    extern __shared__ unsigned sm[];
    unsigned* skeys = sm;                    // [BS_TOK]
    unsigned* whist = sm + BS_TOK;           // [32][256]
    __shared__ unsigned suf[256];
    __shared__ int wsum[32];
    __shared__ unsigned s_prefix;
    __shared__ int s_need, s_out;

    const int e = blockIdx.x;
    const int tid = threadIdx.x, lane = tid & 31, wrp = tid >> 5;
    const unsigned* keys = g_keys + (size_t)e * BS_TOK;

#pragma unroll
    for (int i = 0; i < BS_TOK / (TPK_T * 4); i++) {
        uint4 v = ((const uint4*)keys)[tid + i * TPK_T];
        ((uint4*)skeys)[tid + i * TPK_T] = v;
    }
    if (tid == 0) { s_prefix = 0u; s_need = KCAP; s_out = 0; }
    __syncthreads();

#pragma unroll
    for (int p = 3; p >= 0; p--) {
        {   // zero my warp hist (vectorized)
            uint4 z = make_uint4(0, 0, 0, 0);
#pragma unroll
            for (int i = 0; i < 2; i++)
                ((uint4*)whist)[tid + i * TPK_T] = z;
        }
        __syncthreads();
        const int sh = p * 8;
        const unsigned maskHi = (p == 3) ? 0u : (0xFFFFFFFFu << ((p + 1) * 8));
        const unsigned pref = s_prefix;
        const int need = s_need;
        unsigned* myh = whist + wrp * 256;
#pragma unroll
        for (int i = 0; i < TPK_PER / 4; i++) {
            uint4 kv = ((const uint4*)skeys)[tid + i * TPK_T];
            unsigned ks[4] = {kv.x, kv.y, kv.z, kv.w};
#pragma unroll
            for (int c = 0; c < 4; c++) {
                unsigned k = ks[c];
                bool m = ((k & maskHi) == pref);
                unsigned mm = __ballot_sync(0xffffffffu, m);
                if (mm != 0u) {
                    unsigned bin = m ? ((k >> sh) & 255u) : 0xFFFFFFFFu;
                    unsigned peers = __match_any_sync(0xffffffffu, bin);
                    if (m && lane == (__ffs(peers) - 1))
                        myh[bin] += (unsigned)__popc(peers);
                }
            }
        }
        __syncthreads();
        if (tid < 256) {
            unsigned sv = 0;
#pragma unroll
            for (int w2 = 0; w2 < 32; w2++) sv += whist[w2 * 256 + tid];
            suf[tid] = sv;
        }
        __syncthreads();
        if (wrp == 0) {
            unsigned v[8];
            unsigned tot = 0;
#pragma unroll
            for (int j = 0; j < 8; j++) { v[j] = suf[lane * 8 + j]; tot += v[j]; }
            unsigned sv = tot;
#pragma unroll
            for (int o = 1; o < 32; o <<= 1) {
                unsigned t = __shfl_down_sync(0xffffffffu, sv, o);
                if (lane + o < 32) sv += t;
            }
            unsigned acc = sv - tot;
#pragma unroll
            for (int j = 7; j >= 0; j--) { acc += v[j]; v[j] = acc; }
#pragma unroll
            for (int j = 0; j < 8; j++) suf[lane * 8 + j] = v[j];
        }
        __syncthreads();
        if (tid < 256) {
            unsigned nxt = (tid == 255) ? 0u : suf[tid + 1];
            if ((int)suf[tid] >= need && (int)nxt < need) {
                s_prefix = pref | ((unsigned)tid << sh);
                s_need = need - (int)nxt;
            }
        }
        __syncthreads();
    }

    const unsigned T = s_prefix;
    const int needEq = s_need;

    const int base = tid * TPK_PER;
    unsigned kl[TPK_PER];
#pragma unroll
    for (int j4 = 0; j4 < TPK_PER / 4; j4++) {
        uint4 kv = ((const uint4*)(skeys + base))[j4];
        kl[j4*4]   = kv.x; kl[j4*4+1] = kv.y;
        kl[j4*4+2] = kv.z; kl[j4*4+3] = kv.w;
    }
    int cnt = 0;
#pragma unroll
    for (int j = 0; j < TPK_PER; j++) cnt += (kl[j] == T);
    int inc = cnt;
#pragma unroll
    for (int o = 1; o < 32; o <<= 1) {
        int t = __shfl_up_sync(0xffffffffu, inc, o);
        if (lane >= o) inc += t;
    }
    if (lane == 31) wsum[wrp] = inc;
    __syncthreads();
    if (tid < 32) {
        int v = wsum[tid];
        int sc = v;
#pragma unroll
        for (int o = 1; o < 32; o <<= 1) {
            int t = __shfl_up_sync(0xffffffffu, sc, o);
            if (lane >= o) sc += t;
        }
        wsum[tid] = sc - v;
    }
    __syncthreads();
    int r = wsum[wrp] + inc - cnt;
#pragma unroll
    for (int j = 0; j < TPK_PER; j++) {
        int t = base + j;
        unsigned k = kl[j];
        bool sel;
        if (k > T) sel = true;
        else if (k == T) { sel = (r < needEq); r++; }
        else sel = false;
        if (sel) {
            int slot = atomicAdd(&s_out, 1);
            g_selidx[e * KCAP + slot] = t;
            g_selw  [e * KCAP + slot] = g_scores[(size_t)e * BS_TOK + t];
            g_t2s[t * NEXP + e] = e * KCAP + slot;
        }
    }
}

// ---------------- mma.sync GEMM: 128x256x64 tiles, 4-stage cp.async --------
#define BM 128
#define BN 256
#define BK 64
#define NSTG 4
#define STGB ((BM + BN) * BK * 2)     // 49152 bytes per stage
#define GEMM_SMEM (NSTG * STGB)       // 196608

__device__ __forceinline__ float gelu_f(float v) {
    float u = 0.7978845608028654f * (v + 0.044715f * v * v * v);
    float e = __expf(2.f * u);
    float th = 1.f - __fdividef(2.f, e + 1.f);
    return 0.5f * v * (1.f + th);
}

// EPI==1: g_H = gelu(LN(x)[tok] @ W1^T + b1) bf16.
// EPI==2: g_O[slot] = bf16((acc+b2)*selw).
template <int EPI, int M, int N, int K>
__global__ __launch_bounds__(256, 1) void mma_gemm(const float* __restrict__ bias) {
    extern __shared__ __align__(1024) char smdyn[];
    const int tid = threadIdx.x, wid = tid >> 5, lane = tid & 31;
    const int wm = wid >> 2, wn = wid & 3;           // 2 x 4 warps, 64x64 tiles
    const int e = blockIdx.z;
    uint32_t sb = smem_u32(smdyn);

    const int GX = N / BN;
    int lin = blockIdx.y * GX + blockIdx.x;
    int bm, bn;
    {
        int inb = lin % (8 * GX);
        int g2 = lin / (8 * GX);
        bm = g2 * 8 + (inb & 7);
        bn = inb >> 3;
    }

    const __nv_bfloat16* B = ((EPI == 1) ? g_w1 : g_w2) +
                             ((size_t)e * N + (size_t)bn * BN) * (size_t)K;
    const __nv_bfloat16* A2 = g_H + ((size_t)e * M + (size_t)bm * BM) * (size_t)K;

    __shared__ float bsm[BN];
    __shared__ int stok[BM];          // slot -> token map (EPI==1 gather)
    bsm[tid] = bias[(size_t)e * N + bn * BN + tid];
    if (EPI == 1 && tid < BM) stok[tid] = g_selidx[e * KCAP + bm * BM + tid];
    __syncthreads();

    auto fill = [&](int c, int s) {
        uint32_t abase = sb + s * STGB;
        uint32_t bbase = abase + BM * BK * 2;     // +16KB
        const __nv_bfloat16* gb = B + c * BK;
#pragma unroll
        for (int t = 0; t < 4; t++) {
            int i = tid + t * 256;
            int row = i >> 3, seg = i & 7;
            uint32_t off = (uint32_t)(row * 128 + seg * 16);
            off ^= (off >> 3) & 0x70u;
            const __nv_bfloat16* ga;
            if (EPI == 1)
                ga = g_xln + (size_t)stok[row] * K + c * BK + seg * 8;
            else
                ga = A2 + (size_t)row * K + c * BK + seg * 8;
            asm volatile("cp.async.cg.shared.global [%0], [%1], 16;"
                         :: "r"(abase + off), "l"(ga));
        }
#pragma unroll
        for (int t = 0; t < 8; t++) {
            int i = tid + t * 256;
            int row = i >> 3, seg = i & 7;
            uint32_t off = (uint32_t)(row * 128 + seg * 16);
            off ^= (off >> 3) & 0x70u;
            asm volatile("cp.async.cg.shared.global [%0], [%1], 16;"
                         :: "r"(bbase + off), "l"(gb + (size_t)row * K + seg * 8));
        }
        asm volatile("cp.async.commit_group;" ::: "memory");
    };

    float c[4][8][4];
#pragma unroll
    for (int a = 0; a < 4; a++)
#pragma unroll
        for (int b = 0; b < 8; b++)
#pragma unroll
            for (int d = 0; d < 4; d++) c[a][b][d] = 0.f;

    const int nk = K / BK;
    fill(0, 0); fill(1, 1); fill(2, 2);

    for (int kc = 0; kc < nk; kc++) {
        int rem = nk - 1 - kc;
        if (rem >= 2) cp_wait<2>();
        else if (rem == 1) cp_wait<1>();
        else cp_wait<0>();
        __syncthreads();
        if (kc + 3 < nk) fill(kc + 3, (kc + 3) & 3);

        uint32_t abase = sb + (kc & 3) * STGB;
        uint32_t bbase = abase + BM * BK * 2;

#pragma unroll
        for (int ks = 0; ks < 4; ks++) {
            uint32_t a[4][4], b[8][2];
            int ar = wm * 64 + (lane & 15);
            int ac = ks * 32 + (lane >> 4) * 16;
#pragma unroll
            for (int mi = 0; mi < 4; mi++) {
                uint32_t off = (uint32_t)((ar + mi * 16) * 128 + ac);
                off ^= (off >> 3) & 0x70u;
                asm volatile(
                    "ldmatrix.sync.aligned.m8n8.x4.shared.b16 {%0,%1,%2,%3}, [%4];"
                    : "=r"(a[mi][0]), "=r"(a[mi][1]), "=r"(a[mi][2]), "=r"(a[mi][3])
                    : "r"(abase + off));
            }
            int nr = wn * 64 + (lane & 7) + ((lane >> 4) << 3);
            int kb = ks * 32 + ((lane >> 3) & 1) * 16;
#pragma unroll
            for (int nb = 0; nb < 4; nb++) {
                uint32_t off = (uint32_t)((nr + nb * 16) * 128 + kb);
                off ^= (off >> 3) & 0x70u;
                asm volatile(
                    "ldmatrix.sync.aligned.m8n8.x4.shared.b16 {%0,%1,%2,%3}, [%4];"
                    : "=r"(b[2*nb][0]), "=r"(b[2*nb][1]),
                      "=r"(b[2*nb+1][0]), "=r"(b[2*nb+1][1])
                    : "r"(bbase + off));
            }
#pragma unroll
            for (int mi = 0; mi < 4; mi++)
#pragma unroll
                for (int ni = 0; ni < 8; ni++) {
                    asm volatile(
                        "mma.sync.aligned.m16n8k16.row.col.f32.bf16.bf16.f32 "
                        "{%0,%1,%2,%3}, {%4,%5,%6,%7}, {%8,%9}, {%0,%1,%2,%3};"
                        : "+f"(c[mi][ni][0]), "+f"(c[mi][ni][1]),
                          "+f"(c[mi][ni][2]), "+f"(c[mi][ni][3])
                        : "r"(a[mi][0]), "r"(a[mi][1]), "r"(a[mi][2]), "r"(a[mi][3]),
                          "r"(b[ni][0]), "r"(b[ni][1]));
                }
        }
        __syncthreads();
    }

    // -------- epilogue --------
    int g4 = lane >> 2, tg2 = (lane & 3) * 2;
    if (EPI == 1) {
#pragma unroll
        for (int mi = 0; mi < 4; mi++) {
            int row = bm * BM + wm * 64 + mi * 16 + g4;
            size_t h0 = ((size_t)e * M + row) * (size_t)N;
            size_t h1 = ((size_t)e * M + row + 8) * (size_t)N;
#pragma unroll
            for (int ni = 0; ni < 8; ni++) {
                int lc = wn * 64 + ni * 8 + tg2;
                int col = bn * BN + lc;
                float bb0 = bsm[lc], bb1 = bsm[lc + 1];
                *(__nv_bfloat162*)(g_H + h0 + col) = __floats2bfloat162_rn(
                    gelu_f(c[mi][ni][0] + bb0), gelu_f(c[mi][ni][1] + bb1));
                *(__nv_bfloat162*)(g_H + h1 + col) = __floats2bfloat162_rn(
                    gelu_f(c[mi][ni][2] + bb0), gelu_f(c[mi][ni][3] + bb1));
            }
        }
    } else {
#pragma unroll
        for (int mi = 0; mi < 4; mi++) {
            int row = bm * BM + wm * 64 + mi * 16 + g4;
            float w0 = g_selw[e * KCAP + row];
            float w1 = g_selw[e * KCAP + row + 8];
            size_t o0 = ((size_t)e * M + row) * (size_t)N;
            size_t o1 = ((size_t)e * M + row + 8) * (size_t)N;
#pragma unroll
            for (int ni = 0; ni < 8; ni++) {
                int lc = wn * 64 + ni * 8 + tg2;
                int col = bn * BN + lc;
                float bb0 = bsm[lc], bb1 = bsm[lc + 1];
                *(__nv_bfloat162*)(g_O + o0 + col) = __floats2bfloat162_rn(
                    (c[mi][ni][0] + bb0) * w0, (c[mi][ni][1] + bb1) * w0);
                *(__nv_bfloat162*)(g_O + o1 + col) = __floats2bfloat162_rn(
                    (c[mi][ni][2] + bb0) * w1, (c[mi][ni][3] + bb1) * w1);
            }
        }
    }
}

// ---------------- final combine (4 tokens/block, bf16 g_O) -----------------
__global__ void combine_kernel(const float* __restrict__ x,
                               float* __restrict__ out) {
    int t0 = blockIdx.x * 4;
    int j = threadIdx.x;
    __shared__ int sl[4][NEXP];
    if (j < 4 * NEXP) sl[j >> 3][j & 7] = g_t2s[t0 * NEXP + j];
    float4 a[4];
#pragma unroll
    for (int tk = 0; tk < 4; tk++)
        a[tk] = ((const float4*)(x + (size_t)(t0 + tk) * DIM))[j];
    __syncthreads();
#pragma unroll
    for (int e = 0; e < NEXP; e++) {
#pragma unroll
        for (int tk = 0; tk < 4; tk++) {
            int s = sl[tk][e];
            if (s >= 0) {
                // 4 bf16 = one 8-byte load
                const __nv_bfloat162* op =
                    (const __nv_bfloat162*)(g_O + (size_t)s * DIM) + j * 2;
                float2 o0 = __bfloat1622float2(op[0]);
                float2 o1 = __bfloat1622float2(op[1]);
                a[tk].x += o0.x; a[tk].y += o0.y;
                a[tk].z += o1.x; a[tk].w += o1.y;
            }
        }
    }
#pragma unroll
    for (int tk = 0; tk < 4; tk++)
        ((float4*)(out + (size_t)(t0 + tk) * DIM))[j] = a[tk];
}

// ---------------- launch ---------------------------------------------------
extern "C" void kernel_launch(void* const* d_in, const int* in_sizes, int n_in,
                              void* d_out, int out_size) {
    const float* x   = (const float*)d_in[0];
    const float* gw  = (const float*)d_in[1];
    const float* lnw = (const float*)d_in[2];
    const float* lnb = (const float*)d_in[3];
    const float* fc1 = (const float*)d_in[4];
    const float* b1  = (const float*)d_in[5];
    const float* fc2 = (const float*)d_in[6];
    const float* b2  = (const float*)d_in[7];
    float* out = (float*)d_out;

    cudaFuncSetAttribute(mma_gemm<1, KCAP, DDIM, DIM>,
                         cudaFuncAttributeMaxDynamicSharedMemorySize, GEMM_SMEM);
    cudaFuncSetAttribute(mma_gemm<2, KCAP, DIM, DDIM>,
                         cudaFuncAttributeMaxDynamicSharedMemorySize, GEMM_SMEM);
    cudaFuncSetAttribute(topk_kernel,
                         cudaFuncAttributeMaxDynamicSharedMemorySize, TPK_SMEM);

    // fork: side stream converts w1 (joins GEMM1) then w2 (joins GEMM2,
    // hidden under GEMM1). Main stream: gate_ln -> topk.
    cudaStream_t sB;
    cudaStreamCreateWithFlags(&sB, cudaStreamNonBlocking);
    cudaEvent_t evFork, evW1, evW2;
    cudaEventCreateWithFlags(&evFork, cudaEventDisableTiming);
    cudaEventCreateWithFlags(&evW1,   cudaEventDisableTiming);
    cudaEventCreateWithFlags(&evW2,   cudaEventDisableTiming);

    cudaEventRecord(evFork, 0);
    cudaStreamWaitEvent(sB, evFork, 0);
    convert_w_kernel<<<4096, 256, 0, sB>>>((const float4*)fc1, 1);
    cudaEventRecord(evW1, sB);
    convert_w_kernel<<<4096, 256, 0, sB>>>((const float4*)fc2, 2);
    cudaEventRecord(evW2, sB);

    gate_ln_kernel<<<BS_TOK / 4, 256>>>(x, gw, lnw, lnb);  // scores + x_ln + t2s init
    topk_kernel<<<NEXP, TPK_T, TPK_SMEM>>>();

    cudaStreamWaitEvent(0, evW1, 0);                  // w1 ready
    {   // GEMM1: per expert (2048 x 4096 x 1024), A gathered from x_ln
        dim3 grid(DDIM / BN, KCAP / BM, NEXP);   // (16, 16, 8)
        mma_gemm<1, KCAP, DDIM, DIM><<<grid, 256, GEMM_SMEM>>>(b1);
    }
    cudaStreamWaitEvent(0, evW2, 0);                  // w2 ready
    {   // GEMM2: per expert (2048 x 1024 x 4096), bias + gate scale -> g_O bf16
        dim3 grid(DIM / BN, KCAP / BM, NEXP);    // (4, 16, 8)
        mma_gemm<2, KCAP, DIM, DDIM><<<grid, 256, GEMM_SMEM>>>(b2);
    }
    combine_kernel<<<BS_TOK / 4, 256>>>(x, out);
}

// round 17
// speedup vs baseline: 1.1220x; 1.0126x over previous
#include <cuda_runtime.h>
#include <cuda_bf16.h>
#include <math.h>
#include <stdint.h>

#define BS_TOK 16384
#define DIM    1024
#define DDIM   4096
#define NEXP   8
#define KCAP   2048   // tokens per expert

// ---------------- scratch (device globals; allocation-free rule) ----------
__device__ __align__(16) __nv_bfloat16 g_w1 [(size_t)NEXP * DDIM * DIM]; // 64MB
__device__ __align__(16) __nv_bfloat16 g_w2 [(size_t)NEXP * DIM * DDIM]; // 64MB
__device__ __align__(16) __nv_bfloat16 g_xln[(size_t)BS_TOK * DIM];      // 32MB (token-ordered LN(x))
__device__ __align__(16) __nv_bfloat16 g_H  [(size_t)BS_TOK * DDIM];    // 128MB
__device__ float    g_scores[NEXP * BS_TOK];
__device__ unsigned g_keys  [NEXP * BS_TOK];
__device__ int      g_selidx[BS_TOK];
__device__ float    g_selw  [BS_TOK];

// ---------------- small helpers -------------------------------------------
__device__ __forceinline__ uint32_t smem_u32(const void* p) {
    uint32_t a;
    asm("{ .reg .u64 t; cvta.to.shared.u64 t, %1; cvt.u32.u64 %0, t; }"
        : "=r"(a) : "l"(p));
    return a;
}
template <int N>
__device__ __forceinline__ void cp_wait() {
    asm volatile("cp.async.wait_group %0;" :: "n"(N) : "memory");
}
__device__ __forceinline__ void red_add_v2(float* p, float a, float b) {
    asm volatile("red.global.add.v2.f32 [%0], {%1, %2};"
                 :: "l"(p), "f"(a), "f"(b) : "memory");
}

// ---------------- weight conversion fp32 -> bf16 (one matrix) -------------
__global__ void convert_w_kernel(const float4* __restrict__ src, int which) {
    size_t n = (size_t)NEXP * DDIM * DIM / 4;
    __nv_bfloat162* dst = (which == 1) ? (__nv_bfloat162*)g_w1
                                       : (__nv_bfloat162*)g_w2;
    for (size_t i = (size_t)blockIdx.x * blockDim.x + threadIdx.x; i < n;
         i += (size_t)gridDim.x * blockDim.x) {
        float4 a = src[i];
        dst[2*i]   = __floats2bfloat162_rn(a.x, a.y);
        dst[2*i+1] = __floats2bfloat162_rn(a.z, a.w);
    }
}

// -------- gating + LayerNorm fused: softmax scores + x_ln, 4 tok/block -----
__global__ void gate_ln_kernel(const float* __restrict__ x,
                               const float* __restrict__ gw,
                               const float* __restrict__ lnw,
                               const float* __restrict__ lnb) {
    int t0 = blockIdx.x * 4;
    int tid = threadIdx.x;
    float4 xv[4];
#pragma unroll
    for (int tk = 0; tk < 4; tk++)
        xv[tk] = ((const float4*)(x + (size_t)(t0 + tk) * DIM))[tid];
    float a[4][NEXP];
#pragma unroll
    for (int e = 0; e < NEXP; e++) {
        float4 wv = ((const float4*)(gw + (size_t)e * DIM))[tid];
#pragma unroll
        for (int tk = 0; tk < 4; tk++)
            a[tk][e] = xv[tk].x*wv.x + xv[tk].y*wv.y +
                       xv[tk].z*wv.z + xv[tk].w*wv.w;
    }
    float s[4], q[4];
#pragma unroll
    for (int tk = 0; tk < 4; tk++) {
        s[tk] = xv[tk].x + xv[tk].y + xv[tk].z + xv[tk].w;
        q[tk] = xv[tk].x*xv[tk].x + xv[tk].y*xv[tk].y +
                xv[tk].z*xv[tk].z + xv[tk].w*xv[tk].w;
    }
#pragma unroll
    for (int o = 16; o > 0; o >>= 1) {
#pragma unroll
        for (int tk = 0; tk < 4; tk++) {
#pragma unroll
            for (int e = 0; e < NEXP; e++)
                a[tk][e] += __shfl_xor_sync(0xffffffffu, a[tk][e], o);
            s[tk] += __shfl_xor_sync(0xffffffffu, s[tk], o);
            q[tk] += __shfl_xor_sync(0xffffffffu, q[tk], o);
        }
    }

    __shared__ float sh[4][8][NEXP];
    __shared__ float red[8][8];
    __shared__ float lg[4][NEXP];
    __shared__ float fin[8];
    int w = tid >> 5, l = tid & 31;
    if (l == 0) {
#pragma unroll
        for (int tk = 0; tk < 4; tk++) {
#pragma unroll
            for (int e = 0; e < NEXP; e++) sh[tk][w][e] = a[tk][e];
            red[2*tk][w] = s[tk]; red[2*tk+1][w] = q[tk];
        }
    }
    __syncthreads();
    if (tid < 32) {
        int tk = tid >> 3, e = tid & 7;
        float sv = 0.f;
#pragma unroll
        for (int i = 0; i < 8; i++) sv += sh[tk][i][e];
        lg[tk][e] = sv;
    }
    if (tid >= 32 && tid < 36) {
        int tk = tid - 32;
        float S = 0.f, Q = 0.f;
#pragma unroll
        for (int i = 0; i < 8; i++) { S += red[2*tk][i]; Q += red[2*tk+1][i]; }
        float mu = S * (1.f / DIM);
        float var = Q * (1.f / DIM) - mu * mu;
        fin[2*tk]   = mu;
        fin[2*tk+1] = rsqrtf(var + 1e-5f);
    }
    __syncthreads();
    if (tid < 32) {
        int tk = tid >> 3, e = tid & 7;
        int t = t0 + tk;
        float mx = lg[tk][0];
#pragma unroll
        for (int i = 1; i < NEXP; i++) mx = fmaxf(mx, lg[tk][i]);
        float den = 0.f;
#pragma unroll
        for (int i = 0; i < NEXP; i++) den += expf(lg[tk][i] - mx);
        float sc = expf(lg[tk][e] - mx) / den;
        g_scores[e * BS_TOK + t] = sc;
        unsigned b = __float_as_uint(sc);
        b ^= (b >> 31) ? 0xFFFFFFFFu : 0x80000000u;
        g_keys[e * BS_TOK + t] = b;
    }
    float4 wv = ((const float4*)lnw)[tid];
    float4 bv = ((const float4*)lnb)[tid];
#pragma unroll
    for (int tk = 0; tk < 4; tk++) {
        float mu = fin[2*tk], rs = fin[2*tk+1];
        __nv_bfloat162* y = (__nv_bfloat162*)(g_xln + (size_t)(t0 + tk) * DIM);
        y[tid*2]   = __floats2bfloat162_rn((xv[tk].x-mu)*rs*wv.x + bv.x,
                                           (xv[tk].y-mu)*rs*wv.y + bv.y);
        y[tid*2+1] = __floats2bfloat162_rn((xv[tk].z-mu)*rs*wv.z + bv.z,
                                           (xv[tk].w-mu)*rs*wv.w + bv.w);
    }
}

// ------- per-expert exact top-k: warp hists + ballot-guarded match ---------
#define TPK_T 1024
#define TPK_PER (BS_TOK / TPK_T)            // 16 keys per thread
#define TPK_SMEM (BS_TOK * 4 + 32 * 256 * 4) // 64KB keys + 32KB warp hists

__global__ __launch_bounds__(TPK_T, 1) void topk_kernel() {
    extern __shared__ unsigned sm[];
    unsigned* skeys = sm;                    // [BS_TOK]
    unsigned* whist = sm + BS_TOK;           // [32][256]
    __shared__ unsigned suf[256];
    __shared__ int wsum[32];
    __shared__ unsigned s_prefix;
    __shared__ int s_need, s_out;

    const int e = blockIdx.x;
    const int tid = threadIdx.x, lane = tid & 31, wrp = tid >> 5;
    const unsigned* keys = g_keys + (size_t)e * BS_TOK;

#pragma unroll
    for (int i = 0; i < BS_TOK / (TPK_T * 4); i++) {
        uint4 v = ((const uint4*)keys)[tid + i * TPK_T];
        ((uint4*)skeys)[tid + i * TPK_T] = v;
    }
    if (tid == 0) { s_prefix = 0u; s_need = KCAP; s_out = 0; }
    __syncthreads();

#pragma unroll
    for (int p = 3; p >= 0; p--) {
        {   // zero my warp hist (vectorized)
            uint4 z = make_uint4(0, 0, 0, 0);
#pragma unroll
            for (int i = 0; i < 2; i++)
                ((uint4*)whist)[tid + i * TPK_T] = z;
        }
        __syncthreads();
        const int sh = p * 8;
        const unsigned maskHi = (p == 3) ? 0u : (0xFFFFFFFFu << ((p + 1) * 8));
        const unsigned pref = s_prefix;
        const int need = s_need;
        unsigned* myh = whist + wrp * 256;
#pragma unroll
        for (int i = 0; i < TPK_PER / 4; i++) {
            uint4 kv = ((const uint4*)skeys)[tid + i * TPK_T];
            unsigned ks[4] = {kv.x, kv.y, kv.z, kv.w};
#pragma unroll
            for (int c = 0; c < 4; c++) {
                unsigned k = ks[c];
                bool m = ((k & maskHi) == pref);
                unsigned mm = __ballot_sync(0xffffffffu, m);
                if (mm != 0u) {
                    unsigned bin = m ? ((k >> sh) & 255u) : 0xFFFFFFFFu;
                    unsigned peers = __match_any_sync(0xffffffffu, bin);
                    if (m && lane == (__ffs(peers) - 1))
                        myh[bin] += (unsigned)__popc(peers);
                }
            }
        }
        __syncthreads();
        if (tid < 256) {
            unsigned sv = 0;
#pragma unroll
            for (int w2 = 0; w2 < 32; w2++) sv += whist[w2 * 256 + tid];
            suf[tid] = sv;
        }
        __syncthreads();
        if (wrp == 0) {
            unsigned v[8];
            unsigned tot = 0;
#pragma unroll
            for (int j = 0; j < 8; j++) { v[j] = suf[lane * 8 + j]; tot += v[j]; }
            unsigned sv = tot;
#pragma unroll
            for (int o = 1; o < 32; o <<= 1) {
                unsigned t = __shfl_down_sync(0xffffffffu, sv, o);
                if (lane + o < 32) sv += t;
            }
            unsigned acc = sv - tot;
#pragma unroll
            for (int j = 7; j >= 0; j--) { acc += v[j]; v[j] = acc; }
#pragma unroll
            for (int j = 0; j < 8; j++) suf[lane * 8 + j] = v[j];
        }
        __syncthreads();
        if (tid < 256) {
            unsigned nxt = (tid == 255) ? 0u : suf[tid + 1];
            if ((int)suf[tid] >= need && (int)nxt < need) {
                s_prefix = pref | ((unsigned)tid << sh);
                s_need = need - (int)nxt;
            }
        }
        __syncthreads();
    }

    const unsigned T = s_prefix;
    const int needEq = s_need;

    const int base = tid * TPK_PER;
    unsigned kl[TPK_PER];
#pragma unroll
    for (int j4 = 0; j4 < TPK_PER / 4; j4++) {
        uint4 kv = ((const uint4*)(skeys + base))[j4];
        kl[j4*4]   = kv.x; kl[j4*4+1] = kv.y;
        kl[j4*4+2] = kv.z; kl[j4*4+3] = kv.w;
    }
    int cnt = 0;
#pragma unroll
    for (int j = 0; j < TPK_PER; j++) cnt += (kl[j] == T);
    int inc = cnt;
#pragma unroll
    for (int o = 1; o < 32; o <<= 1) {
        int t = __shfl_up_sync(0xffffffffu, inc, o);
        if (lane >= o) inc += t;
    }
    if (lane == 31) wsum[wrp] = inc;
    __syncthreads();
    if (tid < 32) {
        int v = wsum[tid];
        int sc = v;
#pragma unroll
        for (int o = 1; o < 32; o <<= 1) {
            int t = __shfl_up_sync(0xffffffffu, sc, o);
            if (lane >= o) sc += t;
        }
        wsum[tid] = sc - v;
    }
    __syncthreads();
    int r = wsum[wrp] + inc - cnt;
#pragma unroll
    for (int j = 0; j < TPK_PER; j++) {
        int t = base + j;
        unsigned k = kl[j];
        bool sel;
        if (k > T) sel = true;
        else if (k == T) { sel = (r < needEq); r++; }
        else sel = false;
        if (sel) {
            int slot = atomicAdd(&s_out, 1);
            g_selidx[e * KCAP + slot] = t;
            g_selw  [e * KCAP + slot] = g_scores[(size_t)e * BS_TOK + t];
        }
    }
}

// ---------------- mma.sync GEMM: 128x256x64 tiles, 4-stage cp.async --------
#define BM 128
#define BN 256
#define BK 64
#define NSTG 4
#define STGB ((BM + BN) * BK * 2)     // 49152 bytes per stage
#define GEMM_SMEM (NSTG * STGB)       // 196608

__device__ __forceinline__ float gelu_f(float v) {
    float u = 0.7978845608028654f * (v + 0.044715f * v * v * v);
    float e = __expf(2.f * u);
    float th = 1.f - __fdividef(2.f, e + 1.f);
    return 0.5f * v * (1.f + th);
}

// EPI==1: g_H = gelu(LN(x)[tok] @ W1^T + b1) bf16.
// EPI==2: out[token] += (acc+b2)*selw via red.global.add.v2.f32.
template <int EPI, int M, int N, int K>
__global__ __launch_bounds__(256, 1) void mma_gemm(const float* __restrict__ bias,
                                                   float* __restrict__ outF) {
    extern __shared__ __align__(1024) char smdyn[];
    const int tid = threadIdx.x, wid = tid >> 5, lane = tid & 31;
    const int wm = wid >> 2, wn = wid & 3;           // 2 x 4 warps, 64x64 tiles
    const int e = blockIdx.z;
    uint32_t sb = smem_u32(smdyn);

    const int GX = N / BN;
    int lin = blockIdx.y * GX + blockIdx.x;
    int bm, bn;
    {
        int inb = lin % (8 * GX);
        int g2 = lin / (8 * GX);
        bm = g2 * 8 + (inb & 7);
        bn = inb >> 3;
    }

    const __nv_bfloat16* B = ((EPI == 1) ? g_w1 : g_w2) +
                             ((size_t)e * N + (size_t)bn * BN) * (size_t)K;
    const __nv_bfloat16* A2 = g_H + ((size_t)e * M + (size_t)bm * BM) * (size_t)K;

    __shared__ float bsm[BN];
    __shared__ int stok[BM];          // slot -> token map
    bsm[tid] = bias[(size_t)e * N + bn * BN + tid];
    if (tid < BM) stok[tid] = g_selidx[e * KCAP + bm * BM + tid];
    __syncthreads();

    auto fill = [&](int c, int s) {
        uint32_t abase = sb + s * STGB;
        uint32_t bbase = abase + BM * BK * 2;     // +16KB
        const __nv_bfloat16* gb = B + c * BK;
#pragma unroll
        for (int t = 0; t < 4; t++) {
            int i = tid + t * 256;
            int row = i >> 3, seg = i & 7;
            uint32_t off = (uint32_t)(row * 128 + seg * 16);
            off ^= (off >> 3) & 0x70u;
            const __nv_bfloat16* ga;
            if (EPI == 1)
                ga = g_xln + (size_t)stok[row] * K + c * BK + seg * 8;
            else
                ga = A2 + (size_t)row * K + c * BK + seg * 8;
            asm volatile("cp.async.cg.shared.global [%0], [%1], 16;"
                         :: "r"(abase + off), "l"(ga));
        }
#pragma unroll
        for (int t = 0; t < 8; t++) {
            int i = tid + t * 256;
            int row = i >> 3, seg = i & 7;
            uint32_t off = (uint32_t)(row * 128 + seg * 16);
            off ^= (off >> 3) & 0x70u;
            asm volatile("cp.async.cg.shared.global [%0], [%1], 16;"
                         :: "r"(bbase + off), "l"(gb + (size_t)row * K + seg * 8));
        }
        asm volatile("cp.async.commit_group;" ::: "memory");
    };

    float c[4][8][4];
#pragma unroll
    for (int a = 0; a < 4; a++)
#pragma unroll
        for (int b = 0; b < 8; b++)
#pragma unroll
            for (int d = 0; d < 4; d++) c[a][b][d] = 0.f;

    const int nk = K / BK;
    fill(0, 0); fill(1, 1); fill(2, 2);

    for (int kc = 0; kc < nk; kc++) {
        int rem = nk - 1 - kc;
        if (rem >= 2) cp_wait<2>();
        else if (rem == 1) cp_wait<1>();
        else cp_wait<0>();
        __syncthreads();
        if (kc + 3 < nk) fill(kc + 3, (kc + 3) & 3);

        uint32_t abase = sb + (kc & 3) * STGB;
        uint32_t bbase = abase + BM * BK * 2;

#pragma unroll
        for (int ks = 0; ks < 4; ks++) {
            uint32_t a[4][4], b[8][2];
            int ar = wm * 64 + (lane & 15);
            int ac = ks * 32 + (lane >> 4) * 16;
#pragma unroll
            for (int mi = 0; mi < 4; mi++) {
                uint32_t off = (uint32_t)((ar + mi * 16) * 128 + ac);
                off ^= (off >> 3) & 0x70u;
                asm volatile(
                    "ldmatrix.sync.aligned.m8n8.x4.shared.b16 {%0,%1,%2,%3}, [%4];"
                    : "=r"(a[mi][0]), "=r"(a[mi][1]), "=r"(a[mi][2]), "=r"(a[mi][3])
                    : "r"(abase + off));
            }
            int nr = wn * 64 + (lane & 7) + ((lane >> 4) << 3);
            int kb = ks * 32 + ((lane >> 3) & 1) * 16;
#pragma unroll
            for (int nb = 0; nb < 4; nb++) {
                uint32_t off = (uint32_t)((nr + nb * 16) * 128 + kb);
                off ^= (off >> 3) & 0x70u;
                asm volatile(
                    "ldmatrix.sync.aligned.m8n8.x4.shared.b16 {%0,%1,%2,%3}, [%4];"
                    : "=r"(b[2*nb][0]), "=r"(b[2*nb][1]),
                      "=r"(b[2*nb+1][0]), "=r"(b[2*nb+1][1])
                    : "r"(bbase + off));
            }
#pragma unroll
            for (int mi = 0; mi < 4; mi++)
#pragma unroll
                for (int ni = 0; ni < 8; ni++) {
                    asm volatile(
                        "mma.sync.aligned.m16n8k16.row.col.f32.bf16.bf16.f32 "
                        "{%0,%1,%2,%3}, {%4,%5,%6,%7}, {%8,%9}, {%0,%1,%2,%3};"
                        : "+f"(c[mi][ni][0]), "+f"(c[mi][ni][1]),
                          "+f"(c[mi][ni][2]), "+f"(c[mi][ni][3])
                        : "r"(a[mi][0]), "r"(a[mi][1]), "r"(a[mi][2]), "r"(a[mi][3]),
                          "r"(b[ni][0]), "r"(b[ni][1]));
                }
        }
        __syncthreads();
    }

    // -------- epilogue --------
    int g4 = lane >> 2, tg2 = (lane & 3) * 2;
    if (EPI == 1) {
#pragma unroll
        for (int mi = 0; mi < 4; mi++) {
            int row = bm * BM + wm * 64 + mi * 16 + g4;
            size_t h0 = ((size_t)e * M + row) * (size_t)N;
            size_t h1 = ((size_t)e * M + row + 8) * (size_t)N;
#pragma unroll
            for (int ni = 0; ni < 8; ni++) {
                int lc = wn * 64 + ni * 8 + tg2;
                int col = bn * BN + lc;
                float bb0 = bsm[lc], bb1 = bsm[lc + 1];
                *(__nv_bfloat162*)(g_H + h0 + col) = __floats2bfloat162_rn(
                    gelu_f(c[mi][ni][0] + bb0), gelu_f(c[mi][ni][1] + bb1));
                *(__nv_bfloat162*)(g_H + h1 + col) = __floats2bfloat162_rn(
                    gelu_f(c[mi][ni][2] + bb0), gelu_f(c[mi][ni][3] + bb1));
            }
        }
    } else {
#pragma unroll
        for (int mi = 0; mi < 4; mi++) {
            int row = bm * BM + wm * 64 + mi * 16 + g4;
            int t0 = stok[wm * 64 + mi * 16 + g4];
            int t1 = stok[wm * 64 + mi * 16 + g4 + 8];
            float w0 = g_selw[e * KCAP + row];
            float w1 = g_selw[e * KCAP + row + 8];
            float* d0 = outF + (size_t)t0 * DIM;
            float* d1 = outF + (size_t)t1 * DIM;
#pragma unroll
            for (int ni = 0; ni < 8; ni++) {
                int lc = wn * 64 + ni * 8 + tg2;
                int col = bn * BN + lc;
                float bb0 = bsm[lc], bb1 = bsm[lc + 1];
                red_add_v2(d0 + col, (c[mi][ni][0] + bb0) * w0,
                                     (c[mi][ni][1] + bb1) * w0);
                red_add_v2(d1 + col, (c[mi][ni][2] + bb0) * w1,
                                     (c[mi][ni][3] + bb1) * w1);
            }
        }
    }
}

// ---------------- launch ---------------------------------------------------
extern "C" void kernel_launch(void* const* d_in, const int* in_sizes, int n_in,
                              void* d_out, int out_size) {
    const float* x   = (const float*)d_in[0];
    const float* gw  = (const float*)d_in[1];
    const float* lnw = (const float*)d_in[2];
    const float* lnb = (const float*)d_in[3];
    const float* fc1 = (const float*)d_in[4];
    const float* b1  = (const float*)d_in[5];
    const float* fc2 = (const float*)d_in[6];
    const float* b2  = (const float*)d_in[7];
    float* out = (float*)d_out;

    cudaFuncSetAttribute(mma_gemm<1, KCAP, DDIM, DIM>,
                         cudaFuncAttributeMaxDynamicSharedMemorySize, GEMM_SMEM);
    cudaFuncSetAttribute(mma_gemm<2, KCAP, DIM, DDIM>,
                         cudaFuncAttributeMaxDynamicSharedMemorySize, GEMM_SMEM);
    cudaFuncSetAttribute(topk_kernel,
                         cudaFuncAttributeMaxDynamicSharedMemorySize, TPK_SMEM);

    // fork: side stream converts w1 (joins GEMM1), w2, then seeds out<-x
    // (joins GEMM2; hidden under GEMM1). Main stream: gate_ln -> topk.
    cudaStream_t sB;
    cudaStreamCreateWithFlags(&sB, cudaStreamNonBlocking);
    cudaEvent_t evFork, evW1, evSeed;
    cudaEventCreateWithFlags(&evFork, cudaEventDisableTiming);
    cudaEventCreateWithFlags(&evW1,   cudaEventDisableTiming);
    cudaEventCreateWithFlags(&evSeed, cudaEventDisableTiming);

    cudaEventRecord(evFork, 0);
    cudaStreamWaitEvent(sB, evFork, 0);
    convert_w_kernel<<<4096, 256, 0, sB>>>((const float4*)fc1, 1);
    cudaEventRecord(evW1, sB);
    convert_w_kernel<<<4096, 256, 0, sB>>>((const float4*)fc2, 2);
    cudaMemcpyAsync(out, x, (size_t)BS_TOK * DIM * sizeof(float),
                    cudaMemcpyDeviceToDevice, sB);
    cudaEventRecord(evSeed, sB);

    gate_ln_kernel<<<BS_TOK / 4, 256>>>(x, gw, lnw, lnb);  // scores + x_ln
    topk_kernel<<<NEXP, TPK_T, TPK_SMEM>>>();

    cudaStreamWaitEvent(0, evW1, 0);                  // w1 ready
    {   // GEMM1: per expert (2048 x 4096 x 1024), A gathered from x_ln
        dim3 grid(DDIM / BN, KCAP / BM, NEXP);   // (16, 16, 8)
        mma_gemm<1, KCAP, DDIM, DIM><<<grid, 256, GEMM_SMEM>>>(b1, nullptr);
    }
    cudaStreamWaitEvent(0, evSeed, 0);                // w2 + seeded out ready
    {   // GEMM2: per expert (2048 x 1024 x 4096), bias+scale+v2-scatter
        dim3 grid(DIM / BN, KCAP / BM, NEXP);    // (4, 16, 8)
        mma_gemm<2, KCAP, DIM, DDIM><<<grid, 256, GEMM_SMEM>>>(b2, out);
    }
}